// round 7
// baseline (speedup 1.0000x reference)
#include <cuda_runtime.h>
#include <math.h>

// Problem constants (fixed shapes per reference)
#define CN 100000      // nodes
#define CE 1600000     // edges
#define CG 4096        // graphs
#define CH 128         // hidden
#define CF 32          // input features
#define NB_SCAN 98     // ceil(CN/1024)
#define ASTR 132       // float stride of smem A-tile rows (k-major, FFMA2 gemm32)

// ---------------- device scratch (static, no allocation) ----------------
__device__ __align__(16) int   g_deg[CN];
__device__ __align__(16) int   g_rowptr[CN];
__device__ __align__(16) int   g_cursor[CN];
__device__ __align__(16) int   g_col[CE];
__device__ __align__(16) float g_dinv[CN];
__device__ __align__(16) float g_bufA[(size_t)CN * CH];
__device__ __align__(16) float g_bufB[(size_t)CN * CH];
__device__ __align__(16) float g_sums[6 * CH];   // (sum, sumsq) x 3 layers
__device__ __align__(16) float g_scale[3 * CH];
__device__ __align__(16) float g_shift[3 * CH];
__device__ __align__(16) int   g_bsums[128];

// ---------------- packed fp32x2 helpers (gemm32) ----------------
__device__ __forceinline__ unsigned long long pack2(float lo, float hi) {
    unsigned long long r;
    asm("mov.b64 %0, {%1, %2};" : "=l"(r) : "f"(lo), "f"(hi));
    return r;
}
__device__ __forceinline__ void unpack2(unsigned long long v, float& lo, float& hi) {
    asm("mov.b64 {%0, %1}, %2;" : "=f"(lo), "=f"(hi) : "l"(v));
}
__device__ __forceinline__ void ffma2(unsigned long long& d, unsigned long long a,
                                      unsigned long long b) {
    asm("fma.rn.f32x2 %0, %1, %2, %0;" : "+l"(d) : "l"(a), "l"(b));
}

// ---------------- tf32 helpers ----------------
__device__ __forceinline__ unsigned f2tf32(float f) {
    unsigned r;
    asm("cvt.rna.tf32.f32 %0, %1;" : "=r"(r) : "f"(f));
    return r;
}
__device__ __forceinline__ void mma_tf32(float (&d)[4], const unsigned (&a)[4],
                                         const unsigned (&b)[2]) {
    asm volatile(
        "mma.sync.aligned.m16n8k8.row.col.f32.tf32.tf32.f32 "
        "{%0,%1,%2,%3}, {%4,%5,%6,%7}, {%8,%9}, {%0,%1,%2,%3};"
        : "+f"(d[0]), "+f"(d[1]), "+f"(d[2]), "+f"(d[3])
        : "r"(a[0]), "r"(a[1]), "r"(a[2]), "r"(a[3]), "r"(b[0]), "r"(b[1]));
}

__device__ __forceinline__ float4 bnrelu4(float4 v, float4 sc, float4 sh) {
    float4 r;
    r.x = fmaxf(fmaf(sc.x, v.x, sh.x), 0.f);
    r.y = fmaxf(fmaf(sc.y, v.y, sh.y), 0.f);
    r.z = fmaxf(fmaf(sc.z, v.z, sh.z), 0.f);
    r.w = fmaxf(fmaf(sc.w, v.w, sh.w), 0.f);
    return r;
}

// ---------------- CSR build (edge_index is int32) ----------------
__global__ void k_deg(const int* __restrict__ ei) {
    int e = blockIdx.x * blockDim.x + threadIdx.x;
    if (e < CE) atomicAdd(&g_deg[ei[CE + e]], 1);
}

__global__ void k_scan1() {     // block scan; also dinv + cursor zero
    __shared__ int s[1024];
    int tid = threadIdx.x;
    int i = blockIdx.x * 1024 + tid;
    int v = (i < CN) ? g_deg[i] : 0;
    if (i < CN) {
        g_dinv[i] = rsqrtf((float)(v + 1));   // +1 self loop
        g_cursor[i] = 0;
    }
    s[tid] = v;
    __syncthreads();
    for (int off = 1; off < 1024; off <<= 1) {
        int t = (tid >= off) ? s[tid - off] : 0;
        __syncthreads();
        s[tid] += t;
        __syncthreads();
    }
    if (i < CN) g_rowptr[i] = s[tid] - v;   // exclusive within block
    if (tid == 1023) g_bsums[blockIdx.x] = s[1023];
}

// merged scan2+scan3 (256-thread blocks; arrays sized to blockDim)
__global__ void k_scanfix() {
    __shared__ int s[256];
    __shared__ int sx[256];
    int tid = threadIdx.x;
    int v = (tid < NB_SCAN) ? g_bsums[tid] : 0;
    s[tid] = v;
    __syncthreads();
    for (int off = 1; off < 128; off <<= 1) {
        int t = (tid >= off) ? s[tid - off] : 0;
        __syncthreads();
        s[tid] += t;
        __syncthreads();
    }
    sx[tid] = s[tid] - v;   // exclusive
    __syncthreads();
    int i = blockIdx.x * blockDim.x + tid;
    if (i < CN) g_rowptr[i] += sx[i >> 10];
    if (blockIdx.x == 0)
        for (int j = tid; j < 6 * CH; j += blockDim.x) g_sums[j] = 0.f;
}

__global__ void k_scatter(const int* __restrict__ ei) {
    int e = blockIdx.x * blockDim.x + threadIdx.x;
    if (e < CE) {
        int d = ei[CE + e];
        int p = atomicAdd(&g_cursor[d], 1);
        g_col[g_rowptr[d] + p] = ei[e];
    }
}

// ---------------- aggregation: out = A_norm @ x ----------------
__global__ void __launch_bounds__(256) k_agg32(const float* __restrict__ x) {
    int warp = (blockIdx.x * blockDim.x + threadIdx.x) >> 5;
    if (warp >= CN) return;
    int lane = threadIdx.x & 31;
    float dv = g_dinv[warp];
    float acc = dv * dv * x[(size_t)warp * CF + lane];   // self loop
    int e = g_rowptr[warp];
    int e1 = e + g_deg[warp];
    for (; e + 3 < e1; e += 4) {
        int s0 = g_col[e], s1 = g_col[e + 1], s2 = g_col[e + 2], s3 = g_col[e + 3];
        float w0 = g_dinv[s0] * dv, w1 = g_dinv[s1] * dv;
        float w2 = g_dinv[s2] * dv, w3 = g_dinv[s3] * dv;
        float u0 = x[(size_t)s0 * CF + lane];
        float u1 = x[(size_t)s1 * CF + lane];
        float u2 = x[(size_t)s2 * CF + lane];
        float u3 = x[(size_t)s3 * CF + lane];
        acc = fmaf(w0, u0, acc);
        acc = fmaf(w1, u1, acc);
        acc = fmaf(w2, u2, acc);
        acc = fmaf(w3, u3, acc);
    }
    for (; e < e1; e++) {
        int s = g_col[e];
        acc = fmaf(g_dinv[s] * dv, x[(size_t)s * CF + lane], acc);
    }
    g_bufA[(size_t)warp * CF + lane] = acc;
}

__global__ void __launch_bounds__(256) k_agg128(const float* __restrict__ xin,
                                                const float* __restrict__ scale,
                                                const float* __restrict__ shift,
                                                float* __restrict__ out) {
    int warp = (blockIdx.x * blockDim.x + threadIdx.x) >> 5;
    if (warp >= CN) return;
    int lane = threadIdx.x & 31;
    float4 sc = ((const float4*)scale)[lane];
    float4 sh = ((const float4*)shift)[lane];
    float dv = g_dinv[warp];
    float4 v = ((const float4*)(xin + (size_t)warp * CH))[lane];
    v = bnrelu4(v, sc, sh);
    float dv2 = dv * dv;
    float4 acc = make_float4(dv2 * v.x, dv2 * v.y, dv2 * v.z, dv2 * v.w);
    int e = g_rowptr[warp];
    int e1 = e + g_deg[warp];
    for (; e + 1 < e1; e += 2) {
        int s0 = g_col[e], s1 = g_col[e + 1];
        float w0 = g_dinv[s0] * dv, w1 = g_dinv[s1] * dv;
        float4 u0 = ((const float4*)(xin + (size_t)s0 * CH))[lane];
        float4 u1 = ((const float4*)(xin + (size_t)s1 * CH))[lane];
        u0 = bnrelu4(u0, sc, sh);
        u1 = bnrelu4(u1, sc, sh);
        acc.x = fmaf(w0, u0.x, acc.x); acc.y = fmaf(w0, u0.y, acc.y);
        acc.z = fmaf(w0, u0.z, acc.z); acc.w = fmaf(w0, u0.w, acc.w);
        acc.x = fmaf(w1, u1.x, acc.x); acc.y = fmaf(w1, u1.y, acc.y);
        acc.z = fmaf(w1, u1.z, acc.z); acc.w = fmaf(w1, u1.w, acc.w);
    }
    if (e < e1) {
        int s = g_col[e];
        float w = g_dinv[s] * dv;
        float4 u = ((const float4*)(xin + (size_t)s * CH))[lane];
        u = bnrelu4(u, sc, sh);
        acc.x = fmaf(w, u.x, acc.x); acc.y = fmaf(w, u.y, acc.y);
        acc.z = fmaf(w, u.z, acc.z); acc.w = fmaf(w, u.w, acc.w);
    }
    ((float4*)(out + (size_t)warp * CH))[lane] = acc;
}

// ---------------- GEMM K=32 (layer 0): FFMA2, fused BN stats -------------------
__global__ void __launch_bounds__(256, 2) k_gemm32(const float* __restrict__ A,
                                                   const float* __restrict__ W,
                                                   const float* __restrict__ bias,
                                                   float* __restrict__ out,
                                                   float* __restrict__ sums) {
    extern __shared__ float sm[];
    float* Ws = sm;               // [32][128]
    float* As = sm + 32 * 128;    // [32][ASTR] k-major
    int tid = threadIdx.x;
    int tx = tid & 15;
    int ty = tid >> 4;
    int row0 = blockIdx.x * 128;

    for (int i = tid; i < 32 * 128; i += 256) Ws[i] = W[i];

    unsigned long long acc[8][4];
#pragma unroll
    for (int i = 0; i < 8; i++)
#pragma unroll
        for (int j = 0; j < 4; j++) acc[i][j] = 0ull;

    __syncthreads();
    for (int i = tid; i < 128 * 32; i += 256) {
        int r = i >> 5, k = i & 31;
        int gr = row0 + r;
        float v = (gr < CN) ? A[(size_t)gr * CF + k] : 0.f;
        As[k * ASTR + r] = v;
    }
    __syncthreads();
#pragma unroll
    for (int k = 0; k < 32; k++) {
        float4 a0 = *(const float4*)&As[k * ASTR + ty * 8];
        float4 a1 = *(const float4*)&As[k * ASTR + ty * 8 + 4];
        const ulonglong2* Brow = (const ulonglong2*)&Ws[k * 128 + tx * 8];
        ulonglong2 q0 = Brow[0];
        ulonglong2 q1 = Brow[1];
        unsigned long long bp[4] = {q0.x, q0.y, q1.x, q1.y};
        float av[8] = {a0.x, a0.y, a0.z, a0.w, a1.x, a1.y, a1.z, a1.w};
#pragma unroll
        for (int i = 0; i < 8; i++) {
            unsigned long long ap = pack2(av[i], av[i]);
#pragma unroll
            for (int j = 0; j < 4; j++) ffma2(acc[i][j], ap, bp[j]);
        }
    }

    float4 bj0 = *(const float4*)&bias[tx * 8];
    float4 bj1 = *(const float4*)&bias[tx * 8 + 4];
    float bj[8] = {bj0.x, bj0.y, bj0.z, bj0.w, bj1.x, bj1.y, bj1.z, bj1.w};
    float csum[8], csq[8];
#pragma unroll
    for (int j = 0; j < 8; j++) { csum[j] = 0.f; csq[j] = 0.f; }
#pragma unroll
    for (int i = 0; i < 8; i++) {
        int r = row0 + ty * 8 + i;
        if (r < CN) {
            float v[8];
#pragma unroll
            for (int j = 0; j < 4; j++) unpack2(acc[i][j], v[2 * j], v[2 * j + 1]);
#pragma unroll
            for (int j = 0; j < 8; j++) {
                v[j] += bj[j];
                csum[j] += v[j];
                csq[j] += v[j] * v[j];
            }
            float* orow = out + (size_t)r * 128 + tx * 8;
            *(float4*)&orow[0] = make_float4(v[0], v[1], v[2], v[3]);
            *(float4*)&orow[4] = make_float4(v[4], v[5], v[6], v[7]);
        }
    }
    __syncthreads();
    float* red = sm;
#pragma unroll
    for (int j = 0; j < 8; j++) red[ty * 128 + tx * 8 + j] = csum[j];
    __syncthreads();
    if (tid < 128) {
        float t = 0.f;
#pragma unroll
        for (int q = 0; q < 16; q++) t += red[q * 128 + tid];
        atomicAdd(&sums[tid], t);
    }
    __syncthreads();
#pragma unroll
    for (int j = 0; j < 8; j++) red[ty * 128 + tx * 8 + j] = csq[j];
    __syncthreads();
    if (tid < 128) {
        float t = 0.f;
#pragma unroll
        for (int q = 0; q < 16; q++) t += red[q * 128 + tid];
        atomicAdd(&sums[128 + tid], t);
    }
}

// ---------------- GEMM K=128 via 3xTF32 tensor-core mma ------------------------
// out[N,128] = A[N,128] @ W[128,128] + bias, fused BN stats.
// smem: WH frag [16ch][16nt][32lane][2] u32, WL same, AF frag [16ch][8mt][32lane][4] f32.
__global__ void __launch_bounds__(256, 1) k_gemm128_tf32(const float* __restrict__ A,
                                                         const float* __restrict__ W,
                                                         const float* __restrict__ bias,
                                                         float* __restrict__ out,
                                                         float* __restrict__ sums) {
    extern __shared__ unsigned smu[];
    unsigned* WH = smu;                  // 16384 u32
    unsigned* WL = WH + 16384;           // 16384 u32
    float* AF = (float*)(WL + 16384);    // 16384 f32
    int tid = threadIdx.x;
    int lane = tid & 31;
    int wid = tid >> 5;
    int wm = wid >> 1, wn = wid & 1;     // 4m x 2n warp grid
    int row0 = blockIdx.x * 128;

    // stage W split into fragment layout
    for (int i = tid; i < 16384; i += 256) {
        int k = i >> 7, n = i & 127;
        float v = W[i];
        unsigned hi = f2tf32(v);
        unsigned lo = f2tf32(v - __uint_as_float(hi));
        int addr = ((((k >> 3) << 4) | (n >> 3)) * 32 + (((n & 7) << 2) | (k & 3))) * 2
                   + ((k >> 2) & 1);
        WH[addr] = hi;
        WL[addr] = lo;
    }
    // stage A (f32) into fragment layout
    for (int i = tid; i < 16384; i += 256) {
        int r = i >> 7, k = i & 127;
        int gr = row0 + r;
        float v = (gr < CN) ? A[(size_t)gr * 128 + k] : 0.f;
        int addr = ((((k >> 3) << 3) | (r >> 4)) * 32 + (((r & 7) << 2) | (k & 3))) * 4
                   + ((((k >> 2) & 1) << 1) | ((r >> 3) & 1));
        AF[addr] = v;
    }
    __syncthreads();

    float acc[2][8][4];
#pragma unroll
    for (int mt = 0; mt < 2; mt++)
#pragma unroll
        for (int nt = 0; nt < 8; nt++)
#pragma unroll
            for (int q = 0; q < 4; q++) acc[mt][nt][q] = 0.f;

    for (int ch = 0; ch < 16; ch++) {
        unsigned bh[8][2], bl[8][2];
#pragma unroll
        for (int nt = 0; nt < 8; nt++) {
            int f = ((ch * 16 + wn * 8 + nt) * 32 + lane) * 2;
            uint2 h = *(const uint2*)&WH[f];
            uint2 l = *(const uint2*)&WL[f];
            bh[nt][0] = h.x; bh[nt][1] = h.y;
            bl[nt][0] = l.x; bl[nt][1] = l.y;
        }
#pragma unroll
        for (int mt = 0; mt < 2; mt++) {
            float4 av = *(const float4*)&AF[((ch * 8 + wm * 2 + mt) * 32 + lane) * 4];
            float a4[4] = {av.x, av.y, av.z, av.w};
            unsigned ah[4], al[4];
#pragma unroll
            for (int q = 0; q < 4; q++) {
                ah[q] = f2tf32(a4[q]);
                al[q] = f2tf32(a4[q] - __uint_as_float(ah[q]));
            }
#pragma unroll
            for (int nt = 0; nt < 8; nt++) {
                mma_tf32(acc[mt][nt], ah, bh[nt]);
                mma_tf32(acc[mt][nt], al, bh[nt]);
                mma_tf32(acc[mt][nt], ah, bl[nt]);
            }
        }
    }
    __syncthreads();

    // stats smem (reuse AF region)
    float* ssum = (float*)AF;
    float* ssq = ssum + 128;
    if (tid < 128) { ssum[tid] = 0.f; ssq[tid] = 0.f; }
    __syncthreads();

    int rbase = wm * 32 + (lane >> 2);
    int cb0 = wn * 64 + 2 * (lane & 3);
#pragma unroll
    for (int nt = 0; nt < 8; nt++) {
        int c0 = cb0 + nt * 8;
        float b0 = bias[c0], b1 = bias[c0 + 1];
        float s0 = 0.f, s1 = 0.f, q0 = 0.f, q1 = 0.f;
#pragma unroll
        for (int mt = 0; mt < 2; mt++) {
            int r = row0 + rbase + mt * 16;
            float v0 = acc[mt][nt][0] + b0;
            float v1 = acc[mt][nt][1] + b1;
            float v2 = acc[mt][nt][2] + b0;
            float v3 = acc[mt][nt][3] + b1;
            if (r < CN) {
                *(float2*)&out[(size_t)r * 128 + c0] = make_float2(v0, v1);
                s0 += v0; s1 += v1; q0 += v0 * v0; q1 += v1 * v1;
            }
            if (r + 8 < CN) {
                *(float2*)&out[(size_t)(r + 8) * 128 + c0] = make_float2(v2, v3);
                s0 += v2; s1 += v3; q0 += v2 * v2; q1 += v3 * v3;
            }
        }
#pragma unroll
        for (int off = 16; off >= 4; off >>= 1) {
            s0 += __shfl_down_sync(0xffffffffu, s0, off);
            s1 += __shfl_down_sync(0xffffffffu, s1, off);
            q0 += __shfl_down_sync(0xffffffffu, q0, off);
            q1 += __shfl_down_sync(0xffffffffu, q1, off);
        }
        if (lane < 4) {
            atomicAdd(&ssum[c0], s0);
            atomicAdd(&ssum[c0 + 1], s1);
            atomicAdd(&ssq[c0], q0);
            atomicAdd(&ssq[c0 + 1], q1);
        }
    }
    __syncthreads();
    if (tid < 128) {
        atomicAdd(&sums[tid], ssum[tid]);
        atomicAdd(&sums[128 + tid], ssq[tid]);
    }
}

// ---------------- BN params from stats ----------------
__global__ void k_bnp(const float* __restrict__ sums, const float* __restrict__ g,
                      const float* __restrict__ beta, float* __restrict__ scale,
                      float* __restrict__ shift) {
    int c = threadIdx.x;
    float mean = sums[c] * (1.f / CN);
    float var = sums[128 + c] * (1.f / CN) - mean * mean;
    float sc = g[c] * rsqrtf(var + 1e-5f);
    scale[c] = sc;
    shift[c] = fmaf(-mean, sc, beta[c]);
}

// ---------------- fused pooling + MLP head (batch is sorted) ----------------
__global__ void __launch_bounds__(128) k_poolhead(const int* __restrict__ batch,
                                                  const float* __restrict__ scale,
                                                  const float* __restrict__ shift,
                                                  const float* __restrict__ Wh1,
                                                  const float* __restrict__ bh1,
                                                  const float* __restrict__ Wh2,
                                                  const float* __restrict__ bh2,
                                                  float* __restrict__ out) {
    __shared__ float row[128];
    __shared__ float red[64];
    int g = blockIdx.x;
    int t = threadIdx.x;  // 128 threads

    int lo = 0, hi = CN;
    while (lo < hi) { int m = (lo + hi) >> 1; if (batch[m] < g) lo = m + 1; else hi = m; }
    int start = lo;
    hi = CN;
    while (lo < hi) { int m = (lo + hi) >> 1; if (batch[m] < g + 1) lo = m + 1; else hi = m; }
    int end = lo;

    float sc = scale[t], sh = shift[t];
    float acc = 0.f;
    for (int i = start; i < end; i++)
        acc += fmaxf(fmaf(sc, g_bufB[(size_t)i * CH + t], sh), 0.f);
    float inv = 1.f / fmaxf((float)(end - start), 1.f);
    row[t] = acc * inv;
    __syncthreads();

    if (t < 64) {
        float a = bh1[t];
#pragma unroll 8
        for (int f = 0; f < 128; f++) a = fmaf(row[f], Wh1[f * 64 + t], a);
        a = fmaxf(a, 0.f);
        red[t] = a * Wh2[t];
    }
    __syncthreads();
    if (t < 32) {
        float v = red[t] + red[t + 32];
#pragma unroll
        for (int off = 16; off > 0; off >>= 1)
            v += __shfl_down_sync(0xffffffffu, v, off);
        if (t == 0) out[g] = v + bh2[0];
    }
}

// ---------------- launch ----------------
extern "C" void kernel_launch(void* const* d_in, const int* in_sizes, int n_in,
                              void* d_out, int out_size) {
    const float* x  = (const float*)d_in[0];
    const int* ei   = (const int*)d_in[1];     // int32 (JAX x64 disabled)
    const int* batch= (const int*)d_in[2];     // int32
    const float* W0 = (const float*)d_in[3];
    const float* b0 = (const float*)d_in[4];
    const float* g0 = (const float*)d_in[5];
    const float* be0= (const float*)d_in[6];
    const float* W1 = (const float*)d_in[7];
    const float* b1 = (const float*)d_in[8];
    const float* g1 = (const float*)d_in[9];
    const float* be1= (const float*)d_in[10];
    const float* W2 = (const float*)d_in[11];
    const float* b2 = (const float*)d_in[12];
    const float* g2 = (const float*)d_in[13];
    const float* be2= (const float*)d_in[14];
    const float* Wh1= (const float*)d_in[15];
    const float* bh1= (const float*)d_in[16];
    const float* Wh2= (const float*)d_in[17];
    const float* bh2= (const float*)d_in[18];
    float* out = (float*)d_out;

    void* p;
    cudaGetSymbolAddress(&p, g_deg);    int*   degp  = (int*)p;
    cudaGetSymbolAddress(&p, g_bufA);   float* bufA  = (float*)p;
    cudaGetSymbolAddress(&p, g_bufB);   float* bufB  = (float*)p;
    cudaGetSymbolAddress(&p, g_sums);   float* sums  = (float*)p;
    cudaGetSymbolAddress(&p, g_scale);  float* scale = (float*)p;
    cudaGetSymbolAddress(&p, g_shift);  float* shift = (float*)p;

    const int SM32 = (32 * 128 + 32 * ASTR) * 4;           // 33280 B
    const int SMT  = 16384 * 4 * 2 + 16384 * 4;            // 196608 B
    cudaFuncSetAttribute(k_gemm32, cudaFuncAttributeMaxDynamicSharedMemorySize, SM32);
    cudaFuncSetAttribute(k_gemm128_tf32, cudaFuncAttributeMaxDynamicSharedMemorySize, SMT);

    const int gemmBlocks = (CN + 127) / 128;   // 782
    const int aggBlocks = (CN + 7) / 8;        // 12500

    cudaMemsetAsync(degp, 0, CN * sizeof(int));
    k_deg<<<(CE + 255) / 256, 256>>>(ei);
    k_scan1<<<NB_SCAN, 1024>>>();
    k_scanfix<<<(CN + 255) / 256, 256>>>();
    k_scatter<<<(CE + 255) / 256, 256>>>(ei);

    // Layer 0: aggregate raw x (F=32) then GEMM -> bufB (pre-BN h0) + stats
    k_agg32<<<aggBlocks, 256>>>(x);
    k_gemm32<<<gemmBlocks, 256, SM32>>>(bufA, W0, b0, bufB, sums);
    k_bnp<<<1, 128>>>(sums, g0, be0, scale, shift);

    // Layer 1
    k_agg128<<<aggBlocks, 256>>>(bufB, scale, shift, bufA);
    k_gemm128_tf32<<<gemmBlocks, 256, SMT>>>(bufA, W1, b1, bufB, sums + 256);
    k_bnp<<<1, 128>>>(sums + 256, g1, be1, scale + 128, shift + 128);

    // Layer 2
    k_agg128<<<aggBlocks, 256>>>(bufB, scale + 128, shift + 128, bufA);
    k_gemm128_tf32<<<gemmBlocks, 256, SMT>>>(bufA, W2, b2, bufB, sums + 512);
    k_bnp<<<1, 128>>>(sums + 512, g2, be2, scale + 256, shift + 256);

    // Fused pool + head
    k_poolhead<<<CG, 128>>>(batch, scale + 256, shift + 256, Wh1, bh1, Wh2, bh2, out);
}

// round 8
// speedup vs baseline: 1.0224x; 1.0224x over previous
#include <cuda_runtime.h>
#include <math.h>

// Problem constants (fixed shapes per reference)
#define CN 100000      // nodes
#define CE 1600000     // edges
#define CG 4096        // graphs
#define CH 128         // hidden
#define CF 32          // input features
#define NB_SCAN 98     // ceil(CN/1024)
#define ASTR 132       // float stride of smem A-tile rows (k-major, FFMA2 gemm32)
#define APAD 132       // row-major A tile pad (tf32 gemm)

// ---------------- device scratch (static, no allocation) ----------------
__device__ __align__(16) int   g_deg[CN];
__device__ __align__(16) int   g_rowptr[CN];
__device__ __align__(16) int   g_cursor[CN];
__device__ __align__(16) int   g_col[CE];
__device__ __align__(16) float g_dinv[CN];
__device__ __align__(16) float g_bufA[(size_t)CN * CH];
__device__ __align__(16) float g_bufB[(size_t)CN * CH];
__device__ __align__(16) float g_sums[6 * CH];   // (sum, sumsq) x 3 layers
__device__ __align__(16) float g_scale[3 * CH];
__device__ __align__(16) float g_shift[3 * CH];
__device__ __align__(16) int   g_bsums[128];
__device__ __align__(16) unsigned g_wh[2 * 16384];  // W1/W2 tf32-hi fragments
__device__ __align__(16) unsigned g_wl[2 * 16384];  // W1/W2 tf32-lo fragments

// ---------------- packed fp32x2 helpers (gemm32) ----------------
__device__ __forceinline__ unsigned long long pack2(float lo, float hi) {
    unsigned long long r;
    asm("mov.b64 %0, {%1, %2};" : "=l"(r) : "f"(lo), "f"(hi));
    return r;
}
__device__ __forceinline__ void unpack2(unsigned long long v, float& lo, float& hi) {
    asm("mov.b64 {%0, %1}, %2;" : "=f"(lo), "=f"(hi) : "l"(v));
}
__device__ __forceinline__ void ffma2(unsigned long long& d, unsigned long long a,
                                      unsigned long long b) {
    asm("fma.rn.f32x2 %0, %1, %2, %0;" : "+l"(d) : "l"(a), "l"(b));
}

// ---------------- tf32 helpers ----------------
__device__ __forceinline__ unsigned f2tf32(float f) {
    unsigned r;
    asm("cvt.rna.tf32.f32 %0, %1;" : "=r"(r) : "f"(f));
    return r;
}
__device__ __forceinline__ void mma_tf32(float (&d)[4], const unsigned (&a)[4],
                                         const unsigned (&b)[2]) {
    asm volatile(
        "mma.sync.aligned.m16n8k8.row.col.f32.tf32.tf32.f32 "
        "{%0,%1,%2,%3}, {%4,%5,%6,%7}, {%8,%9}, {%0,%1,%2,%3};"
        : "+f"(d[0]), "+f"(d[1]), "+f"(d[2]), "+f"(d[3])
        : "r"(a[0]), "r"(a[1]), "r"(a[2]), "r"(a[3]), "r"(b[0]), "r"(b[1]));
}

__device__ __forceinline__ float4 bnrelu4(float4 v, float4 sc, float4 sh) {
    float4 r;
    r.x = fmaxf(fmaf(sc.x, v.x, sh.x), 0.f);
    r.y = fmaxf(fmaf(sc.y, v.y, sh.y), 0.f);
    r.z = fmaxf(fmaf(sc.z, v.z, sh.z), 0.f);
    r.w = fmaxf(fmaf(sc.w, v.w, sh.w), 0.f);
    return r;
}

// ---------------- CSR build (edge_index is int32) ----------------
__global__ void k_deg(const int* __restrict__ ei) {
    int e = blockIdx.x * blockDim.x + threadIdx.x;
    if (e < CE) atomicAdd(&g_deg[ei[CE + e]], 1);
}

__global__ void k_scan1() {     // block scan; also dinv + cursor zero
    __shared__ int s[1024];
    int tid = threadIdx.x;
    int i = blockIdx.x * 1024 + tid;
    int v = (i < CN) ? g_deg[i] : 0;
    if (i < CN) {
        g_dinv[i] = rsqrtf((float)(v + 1));   // +1 self loop
        g_cursor[i] = 0;
    }
    s[tid] = v;
    __syncthreads();
    for (int off = 1; off < 1024; off <<= 1) {
        int t = (tid >= off) ? s[tid - off] : 0;
        __syncthreads();
        s[tid] += t;
        __syncthreads();
    }
    if (i < CN) g_rowptr[i] = s[tid] - v;   // exclusive within block
    if (tid == 1023) g_bsums[blockIdx.x] = s[1023];
}

// merged scan2+scan3 (256-thread blocks; arrays sized to blockDim)
__global__ void k_scanfix() {
    __shared__ int s[256];
    __shared__ int sx[256];
    int tid = threadIdx.x;
    int v = (tid < NB_SCAN) ? g_bsums[tid] : 0;
    s[tid] = v;
    __syncthreads();
    for (int off = 1; off < 128; off <<= 1) {
        int t = (tid >= off) ? s[tid - off] : 0;
        __syncthreads();
        s[tid] += t;
        __syncthreads();
    }
    sx[tid] = s[tid] - v;   // exclusive
    __syncthreads();
    int i = blockIdx.x * blockDim.x + tid;
    if (i < CN) g_rowptr[i] += sx[i >> 10];
    if (blockIdx.x == 0)
        for (int j = tid; j < 6 * CH; j += blockDim.x) g_sums[j] = 0.f;
}

__global__ void k_scatter(const int* __restrict__ ei) {
    int e = blockIdx.x * blockDim.x + threadIdx.x;
    if (e < CE) {
        int d = ei[CE + e];
        int p = atomicAdd(&g_cursor[d], 1);
        g_col[g_rowptr[d] + p] = ei[e];
    }
}

// ---------------- W fragment precompute (once; gather-style, coalesced writes) --
// Inverse of: addr = (((k>>3)<<4 | (n>>3))*32 + (((n&7)<<2)|(k&3)))*2 + ((k>>2)&1)
__global__ void k_wsplit(const float* __restrict__ W1, const float* __restrict__ W2) {
    int a = blockIdx.x * blockDim.x + threadIdx.x;   // 0..32767
    if (a >= 2 * 16384) return;
    int layer = a >> 14;
    int t = a & 16383;
    int h = t & 1;
    int u = t >> 1;
    int q = u & 31;
    int slot = u >> 5;
    int k = ((slot >> 4) << 3) | (h << 2) | (q & 3);
    int n = ((slot & 15) << 3) | (q >> 2);
    const float* W = layer ? W2 : W1;
    float v = W[k * 128 + n];
    unsigned hi = f2tf32(v);
    unsigned lo = f2tf32(v - __uint_as_float(hi));
    g_wh[a] = hi;
    g_wl[a] = lo;
}

// ---------------- aggregation: out = A_norm @ x ----------------
__global__ void __launch_bounds__(256) k_agg32(const float* __restrict__ x) {
    int warp = (blockIdx.x * blockDim.x + threadIdx.x) >> 5;
    if (warp >= CN) return;
    int lane = threadIdx.x & 31;
    float dv = g_dinv[warp];
    float acc = dv * dv * x[(size_t)warp * CF + lane];   // self loop
    int e = g_rowptr[warp];
    int e1 = e + g_deg[warp];
    for (; e + 3 < e1; e += 4) {
        int s0 = g_col[e], s1 = g_col[e + 1], s2 = g_col[e + 2], s3 = g_col[e + 3];
        float w0 = g_dinv[s0] * dv, w1 = g_dinv[s1] * dv;
        float w2 = g_dinv[s2] * dv, w3 = g_dinv[s3] * dv;
        float u0 = x[(size_t)s0 * CF + lane];
        float u1 = x[(size_t)s1 * CF + lane];
        float u2 = x[(size_t)s2 * CF + lane];
        float u3 = x[(size_t)s3 * CF + lane];
        acc = fmaf(w0, u0, acc);
        acc = fmaf(w1, u1, acc);
        acc = fmaf(w2, u2, acc);
        acc = fmaf(w3, u3, acc);
    }
    for (; e < e1; e++) {
        int s = g_col[e];
        acc = fmaf(g_dinv[s] * dv, x[(size_t)s * CF + lane], acc);
    }
    g_bufA[(size_t)warp * CF + lane] = acc;
}

__global__ void __launch_bounds__(256) k_agg128(const float* __restrict__ xin,
                                                const float* __restrict__ scale,
                                                const float* __restrict__ shift,
                                                float* __restrict__ out) {
    int warp = (blockIdx.x * blockDim.x + threadIdx.x) >> 5;
    if (warp >= CN) return;
    int lane = threadIdx.x & 31;
    float4 sc = ((const float4*)scale)[lane];
    float4 sh = ((const float4*)shift)[lane];
    float dv = g_dinv[warp];
    float4 v = ((const float4*)(xin + (size_t)warp * CH))[lane];
    v = bnrelu4(v, sc, sh);
    float dv2 = dv * dv;
    float4 acc = make_float4(dv2 * v.x, dv2 * v.y, dv2 * v.z, dv2 * v.w);
    int e = g_rowptr[warp];
    int e1 = e + g_deg[warp];
    for (; e + 1 < e1; e += 2) {
        int s0 = g_col[e], s1 = g_col[e + 1];
        float w0 = g_dinv[s0] * dv, w1 = g_dinv[s1] * dv;
        float4 u0 = ((const float4*)(xin + (size_t)s0 * CH))[lane];
        float4 u1 = ((const float4*)(xin + (size_t)s1 * CH))[lane];
        u0 = bnrelu4(u0, sc, sh);
        u1 = bnrelu4(u1, sc, sh);
        acc.x = fmaf(w0, u0.x, acc.x); acc.y = fmaf(w0, u0.y, acc.y);
        acc.z = fmaf(w0, u0.z, acc.z); acc.w = fmaf(w0, u0.w, acc.w);
        acc.x = fmaf(w1, u1.x, acc.x); acc.y = fmaf(w1, u1.y, acc.y);
        acc.z = fmaf(w1, u1.z, acc.z); acc.w = fmaf(w1, u1.w, acc.w);
    }
    if (e < e1) {
        int s = g_col[e];
        float w = g_dinv[s] * dv;
        float4 u = ((const float4*)(xin + (size_t)s * CH))[lane];
        u = bnrelu4(u, sc, sh);
        acc.x = fmaf(w, u.x, acc.x); acc.y = fmaf(w, u.y, acc.y);
        acc.z = fmaf(w, u.z, acc.z); acc.w = fmaf(w, u.w, acc.w);
    }
    ((float4*)(out + (size_t)warp * CH))[lane] = acc;
}

// ---------------- GEMM K=32 (layer 0): FFMA2, fused BN stats -------------------
__global__ void __launch_bounds__(256, 2) k_gemm32(const float* __restrict__ A,
                                                   const float* __restrict__ W,
                                                   const float* __restrict__ bias,
                                                   float* __restrict__ out,
                                                   float* __restrict__ sums) {
    extern __shared__ float sm[];
    float* Ws = sm;               // [32][128]
    float* As = sm + 32 * 128;    // [32][ASTR] k-major
    int tid = threadIdx.x;
    int tx = tid & 15;
    int ty = tid >> 4;
    int row0 = blockIdx.x * 128;

    for (int i = tid; i < 32 * 128; i += 256) Ws[i] = W[i];

    unsigned long long acc[8][4];
#pragma unroll
    for (int i = 0; i < 8; i++)
#pragma unroll
        for (int j = 0; j < 4; j++) acc[i][j] = 0ull;

    __syncthreads();
    for (int i = tid; i < 128 * 32; i += 256) {
        int r = i >> 5, k = i & 31;
        int gr = row0 + r;
        float v = (gr < CN) ? A[(size_t)gr * CF + k] : 0.f;
        As[k * ASTR + r] = v;
    }
    __syncthreads();
#pragma unroll
    for (int k = 0; k < 32; k++) {
        float4 a0 = *(const float4*)&As[k * ASTR + ty * 8];
        float4 a1 = *(const float4*)&As[k * ASTR + ty * 8 + 4];
        const ulonglong2* Brow = (const ulonglong2*)&Ws[k * 128 + tx * 8];
        ulonglong2 q0 = Brow[0];
        ulonglong2 q1 = Brow[1];
        unsigned long long bp[4] = {q0.x, q0.y, q1.x, q1.y};
        float av[8] = {a0.x, a0.y, a0.z, a0.w, a1.x, a1.y, a1.z, a1.w};
#pragma unroll
        for (int i = 0; i < 8; i++) {
            unsigned long long ap = pack2(av[i], av[i]);
#pragma unroll
            for (int j = 0; j < 4; j++) ffma2(acc[i][j], ap, bp[j]);
        }
    }

    float4 bj0 = *(const float4*)&bias[tx * 8];
    float4 bj1 = *(const float4*)&bias[tx * 8 + 4];
    float bj[8] = {bj0.x, bj0.y, bj0.z, bj0.w, bj1.x, bj1.y, bj1.z, bj1.w};
    float csum[8], csq[8];
#pragma unroll
    for (int j = 0; j < 8; j++) { csum[j] = 0.f; csq[j] = 0.f; }
#pragma unroll
    for (int i = 0; i < 8; i++) {
        int r = row0 + ty * 8 + i;
        if (r < CN) {
            float v[8];
#pragma unroll
            for (int j = 0; j < 4; j++) unpack2(acc[i][j], v[2 * j], v[2 * j + 1]);
#pragma unroll
            for (int j = 0; j < 8; j++) {
                v[j] += bj[j];
                csum[j] += v[j];
                csq[j] += v[j] * v[j];
            }
            float* orow = out + (size_t)r * 128 + tx * 8;
            *(float4*)&orow[0] = make_float4(v[0], v[1], v[2], v[3]);
            *(float4*)&orow[4] = make_float4(v[4], v[5], v[6], v[7]);
        }
    }
    __syncthreads();
    float* red = sm;
#pragma unroll
    for (int j = 0; j < 8; j++) red[ty * 128 + tx * 8 + j] = csum[j];
    __syncthreads();
    if (tid < 128) {
        float t = 0.f;
#pragma unroll
        for (int q = 0; q < 16; q++) t += red[q * 128 + tid];
        atomicAdd(&sums[tid], t);
    }
    __syncthreads();
#pragma unroll
    for (int j = 0; j < 8; j++) red[ty * 128 + tx * 8 + j] = csq[j];
    __syncthreads();
    if (tid < 128) {
        float t = 0.f;
#pragma unroll
        for (int q = 0; q < 16; q++) t += red[q * 128 + tid];
        atomicAdd(&sums[128 + tid], t);
    }
}

// ---------------- GEMM K=128 via 3xTF32 tensor-core mma ------------------------
// W fragments precomputed in global (g_wh/g_wl) -> linear smem copy.
// A staged row-major padded [128][APAD]; fragment LDS provably conflict-free.
__global__ void __launch_bounds__(256, 1) k_gemm128_tf32(const float* __restrict__ A,
                                                         const unsigned* __restrict__ whg,
                                                         const unsigned* __restrict__ wlg,
                                                         const float* __restrict__ bias,
                                                         float* __restrict__ out,
                                                         float* __restrict__ sums) {
    extern __shared__ unsigned smu[];
    unsigned* WH = smu;                  // 16384 u32
    unsigned* WL = WH + 16384;           // 16384 u32
    float* AF = (float*)(WL + 16384);    // [128][APAD] f32
    int tid = threadIdx.x;
    int lane = tid & 31;
    int wid = tid >> 5;
    int wm = wid >> 1, wn = wid & 1;     // 4m x 2n warp grid
    int row0 = blockIdx.x * 128;

    // linear copies (coalesced, no conversion, no scatter)
    for (int i = tid; i < 16384; i += 256) {
        WH[i] = whg[i];
        WL[i] = wlg[i];
    }
    for (int i = tid; i < 16384; i += 256) {
        int r = i >> 7, k = i & 127;
        int gr = row0 + r;
        AF[r * APAD + k] = (gr < CN) ? A[(size_t)gr * 128 + k] : 0.f;
    }
    __syncthreads();

    float acc[2][8][4];
#pragma unroll
    for (int mt = 0; mt < 2; mt++)
#pragma unroll
        for (int nt = 0; nt < 8; nt++)
#pragma unroll
            for (int q = 0; q < 4; q++) acc[mt][nt][q] = 0.f;

    for (int ch = 0; ch < 16; ch++) {
        unsigned bh[8][2], bl[8][2];
#pragma unroll
        for (int nt = 0; nt < 8; nt++) {
            int f = ((ch * 16 + wn * 8 + nt) * 32 + lane) * 2;
            uint2 h = *(const uint2*)&WH[f];
            uint2 l = *(const uint2*)&WL[f];
            bh[nt][0] = h.x; bh[nt][1] = h.y;
            bl[nt][0] = l.x; bl[nt][1] = l.y;
        }
#pragma unroll
        for (int mt = 0; mt < 2; mt++) {
            int base = (wm * 32 + mt * 16 + (lane >> 2)) * APAD + ch * 8 + (lane & 3);
            float a4[4];
            a4[0] = AF[base];                  // (row, k)
            a4[1] = AF[base + 8 * APAD];       // (row+8, k)
            a4[2] = AF[base + 4];              // (row, k+4)
            a4[3] = AF[base + 8 * APAD + 4];   // (row+8, k+4)
            unsigned ah[4], al[4];
#pragma unroll
            for (int q = 0; q < 4; q++) {
                ah[q] = f2tf32(a4[q]);
                al[q] = f2tf32(a4[q] - __uint_as_float(ah[q]));
            }
#pragma unroll
            for (int nt = 0; nt < 8; nt++) {
                mma_tf32(acc[mt][nt], ah, bh[nt]);
                mma_tf32(acc[mt][nt], al, bh[nt]);
                mma_tf32(acc[mt][nt], ah, bl[nt]);
            }
        }
    }
    __syncthreads();

    // stats smem (reuse AF region)
    float* ssum = AF;
    float* ssq = ssum + 128;
    if (tid < 128) { ssum[tid] = 0.f; ssq[tid] = 0.f; }
    __syncthreads();

    int rbase = wm * 32 + (lane >> 2);
    int cb0 = wn * 64 + 2 * (lane & 3);
#pragma unroll
    for (int nt = 0; nt < 8; nt++) {
        int c0 = cb0 + nt * 8;
        float b0 = bias[c0], b1 = bias[c0 + 1];
        float s0 = 0.f, s1 = 0.f, q0 = 0.f, q1 = 0.f;
#pragma unroll
        for (int mt = 0; mt < 2; mt++) {
            int r = row0 + rbase + mt * 16;
            float v0 = acc[mt][nt][0] + b0;
            float v1 = acc[mt][nt][1] + b1;
            float v2 = acc[mt][nt][2] + b0;
            float v3 = acc[mt][nt][3] + b1;
            if (r < CN) {
                *(float2*)&out[(size_t)r * 128 + c0] = make_float2(v0, v1);
                s0 += v0; s1 += v1; q0 += v0 * v0; q1 += v1 * v1;
            }
            if (r + 8 < CN) {
                *(float2*)&out[(size_t)(r + 8) * 128 + c0] = make_float2(v2, v3);
                s0 += v2; s1 += v3; q0 += v2 * v2; q1 += v3 * v3;
            }
        }
#pragma unroll
        for (int off = 16; off >= 4; off >>= 1) {
            s0 += __shfl_down_sync(0xffffffffu, s0, off);
            s1 += __shfl_down_sync(0xffffffffu, s1, off);
            q0 += __shfl_down_sync(0xffffffffu, q0, off);
            q1 += __shfl_down_sync(0xffffffffu, q1, off);
        }
        if (lane < 4) {
            atomicAdd(&ssum[c0], s0);
            atomicAdd(&ssum[c0 + 1], s1);
            atomicAdd(&ssq[c0], q0);
            atomicAdd(&ssq[c0 + 1], q1);
        }
    }
    __syncthreads();
    if (tid < 128) {
        atomicAdd(&sums[tid], ssum[tid]);
        atomicAdd(&sums[128 + tid], ssq[tid]);
    }
}

// ---------------- BN params from stats ----------------
__global__ void k_bnp(const float* __restrict__ sums, const float* __restrict__ g,
                      const float* __restrict__ beta, float* __restrict__ scale,
                      float* __restrict__ shift) {
    int c = threadIdx.x;
    float mean = sums[c] * (1.f / CN);
    float var = sums[128 + c] * (1.f / CN) - mean * mean;
    float sc = g[c] * rsqrtf(var + 1e-5f);
    scale[c] = sc;
    shift[c] = fmaf(-mean, sc, beta[c]);
}

// ---------------- fused pooling + MLP head (batch is sorted) ----------------
__global__ void __launch_bounds__(128) k_poolhead(const int* __restrict__ batch,
                                                  const float* __restrict__ scale,
                                                  const float* __restrict__ shift,
                                                  const float* __restrict__ Wh1,
                                                  const float* __restrict__ bh1,
                                                  const float* __restrict__ Wh2,
                                                  const float* __restrict__ bh2,
                                                  float* __restrict__ out) {
    __shared__ float row[128];
    __shared__ float red[64];
    int g = blockIdx.x;
    int t = threadIdx.x;  // 128 threads

    int lo = 0, hi = CN;
    while (lo < hi) { int m = (lo + hi) >> 1; if (batch[m] < g) lo = m + 1; else hi = m; }
    int start = lo;
    hi = CN;
    while (lo < hi) { int m = (lo + hi) >> 1; if (batch[m] < g + 1) lo = m + 1; else hi = m; }
    int end = lo;

    float sc = scale[t], sh = shift[t];
    float acc = 0.f;
    for (int i = start; i < end; i++)
        acc += fmaxf(fmaf(sc, g_bufB[(size_t)i * CH + t], sh), 0.f);
    float inv = 1.f / fmaxf((float)(end - start), 1.f);
    row[t] = acc * inv;
    __syncthreads();

    if (t < 64) {
        float a = bh1[t];
#pragma unroll 8
        for (int f = 0; f < 128; f++) a = fmaf(row[f], Wh1[f * 64 + t], a);
        a = fmaxf(a, 0.f);
        red[t] = a * Wh2[t];
    }
    __syncthreads();
    if (t < 32) {
        float v = red[t] + red[t + 32];
#pragma unroll
        for (int off = 16; off > 0; off >>= 1)
            v += __shfl_down_sync(0xffffffffu, v, off);
        if (t == 0) out[g] = v + bh2[0];
    }
}

// ---------------- launch ----------------
extern "C" void kernel_launch(void* const* d_in, const int* in_sizes, int n_in,
                              void* d_out, int out_size) {
    const float* x  = (const float*)d_in[0];
    const int* ei   = (const int*)d_in[1];     // int32 (JAX x64 disabled)
    const int* batch= (const int*)d_in[2];     // int32
    const float* W0 = (const float*)d_in[3];
    const float* b0 = (const float*)d_in[4];
    const float* g0 = (const float*)d_in[5];
    const float* be0= (const float*)d_in[6];
    const float* W1 = (const float*)d_in[7];
    const float* b1 = (const float*)d_in[8];
    const float* g1 = (const float*)d_in[9];
    const float* be1= (const float*)d_in[10];
    const float* W2 = (const float*)d_in[11];
    const float* b2 = (const float*)d_in[12];
    const float* g2 = (const float*)d_in[13];
    const float* be2= (const float*)d_in[14];
    const float* Wh1= (const float*)d_in[15];
    const float* bh1= (const float*)d_in[16];
    const float* Wh2= (const float*)d_in[17];
    const float* bh2= (const float*)d_in[18];
    float* out = (float*)d_out;

    void* p;
    cudaGetSymbolAddress(&p, g_deg);    int*   degp  = (int*)p;
    cudaGetSymbolAddress(&p, g_bufA);   float* bufA  = (float*)p;
    cudaGetSymbolAddress(&p, g_bufB);   float* bufB  = (float*)p;
    cudaGetSymbolAddress(&p, g_sums);   float* sums  = (float*)p;
    cudaGetSymbolAddress(&p, g_scale);  float* scale = (float*)p;
    cudaGetSymbolAddress(&p, g_shift);  float* shift = (float*)p;
    cudaGetSymbolAddress(&p, g_wh);     unsigned* whp = (unsigned*)p;
    cudaGetSymbolAddress(&p, g_wl);     unsigned* wlp = (unsigned*)p;

    const int SM32 = (32 * 128 + 32 * ASTR) * 4;            // 33280 B
    const int SMT  = 16384 * 4 * 2 + 128 * APAD * 4;        // 131072 + 67584 = 198656 B
    cudaFuncSetAttribute(k_gemm32, cudaFuncAttributeMaxDynamicSharedMemorySize, SM32);
    cudaFuncSetAttribute(k_gemm128_tf32, cudaFuncAttributeMaxDynamicSharedMemorySize, SMT);

    const int gemmBlocks = (CN + 127) / 128;   // 782
    const int aggBlocks = (CN + 7) / 8;        // 12500

    cudaMemsetAsync(degp, 0, CN * sizeof(int));
    k_deg<<<(CE + 255) / 256, 256>>>(ei);
    k_scan1<<<NB_SCAN, 1024>>>();
    k_scanfix<<<(CN + 255) / 256, 256>>>();
    k_scatter<<<(CE + 255) / 256, 256>>>(ei);
    k_wsplit<<<128, 256>>>(W1, W2);

    // Layer 0: aggregate raw x (F=32) then GEMM -> bufB (pre-BN h0) + stats
    k_agg32<<<aggBlocks, 256>>>(x);
    k_gemm32<<<gemmBlocks, 256, SM32>>>(bufA, W0, b0, bufB, sums);
    k_bnp<<<1, 128>>>(sums, g0, be0, scale, shift);

    // Layer 1
    k_agg128<<<aggBlocks, 256>>>(bufB, scale, shift, bufA);
    k_gemm128_tf32<<<gemmBlocks, 256, SMT>>>(bufA, whp, wlp, b1, bufB, sums + 256);
    k_bnp<<<1, 128>>>(sums + 256, g1, be1, scale + 128, shift + 128);

    // Layer 2
    k_agg128<<<aggBlocks, 256>>>(bufB, scale + 128, shift + 128, bufA);
    k_gemm128_tf32<<<gemmBlocks, 256, SMT>>>(bufA, whp + 16384, wlp + 16384, b2, bufB,
                                             sums + 512);
    k_bnp<<<1, 128>>>(sums + 512, g2, be2, scale + 256, shift + 256);

    // Fused pool + head
    k_poolhead<<<CG, 128>>>(batch, scale + 256, shift + 256, Wh1, bh1, Wh2, bh2, out);
}

// round 11
// speedup vs baseline: 1.2255x; 1.1987x over previous
#include <cuda_runtime.h>
#include <math.h>

// Problem constants (fixed shapes per reference)
#define CN 100000      // nodes
#define CE 1600000     // edges
#define CG 4096        // graphs
#define CH 128         // hidden
#define CF 32          // input features
#define NB_SCAN 98     // ceil(CN/1024)
#define ASTR 132       // float stride of smem A-tile rows (k-major)

// ---------------- device scratch (static, no allocation) ----------------
__device__ __align__(16) int   g_deg[CN];
__device__ __align__(16) int   g_rowptr[CN];
__device__ __align__(16) int   g_cursor[CN];
__device__ __align__(16) int   g_col[CE];
__device__ __align__(16) float g_dinv[CN];
__device__ __align__(16) float g_bufA[(size_t)CN * CH];
__device__ __align__(16) float g_bufB[(size_t)CN * CH];
__device__ __align__(16) float g_sums[6 * CH];   // (sum, sumsq) x 3 layers
__device__ __align__(16) float g_scale[3 * CH];
__device__ __align__(16) float g_shift[3 * CH];
__device__ __align__(16) int   g_bsums[128];

// ---------------- packed fp32x2 helpers ----------------
__device__ __forceinline__ unsigned long long pack2(float lo, float hi) {
    unsigned long long r;
    asm("mov.b64 %0, {%1, %2};" : "=l"(r) : "f"(lo), "f"(hi));
    return r;
}
__device__ __forceinline__ void unpack2(unsigned long long v, float& lo, float& hi) {
    asm("mov.b64 {%0, %1}, %2;" : "=f"(lo), "=f"(hi) : "l"(v));
}
__device__ __forceinline__ void ffma2(unsigned long long& d, unsigned long long a,
                                      unsigned long long b) {
    asm("fma.rn.f32x2 %0, %1, %2, %0;" : "+l"(d) : "l"(a), "l"(b));
}

__device__ __forceinline__ float4 bnrelu4(float4 v, float4 sc, float4 sh) {
    float4 r;
    r.x = fmaxf(fmaf(sc.x, v.x, sh.x), 0.f);
    r.y = fmaxf(fmaf(sc.y, v.y, sh.y), 0.f);
    r.z = fmaxf(fmaf(sc.z, v.z, sh.z), 0.f);
    r.w = fmaxf(fmaf(sc.w, v.w, sh.w), 0.f);
    return r;
}

// ---------------- CSR build (edge_index is int32) ----------------
__global__ void k_deg(const int* __restrict__ ei) {
    int e = blockIdx.x * blockDim.x + threadIdx.x;
    if (e < CE) atomicAdd(&g_deg[ei[CE + e]], 1);
}

__global__ void k_scan1() {     // block scan; also dinv + cursor zero
    __shared__ int s[1024];
    int tid = threadIdx.x;
    int i = blockIdx.x * 1024 + tid;
    int v = (i < CN) ? g_deg[i] : 0;
    if (i < CN) {
        g_dinv[i] = rsqrtf((float)(v + 1));   // +1 self loop
        g_cursor[i] = 0;
    }
    s[tid] = v;
    __syncthreads();
    for (int off = 1; off < 1024; off <<= 1) {
        int t = (tid >= off) ? s[tid - off] : 0;
        __syncthreads();
        s[tid] += t;
        __syncthreads();
    }
    if (i < CN) g_rowptr[i] = s[tid] - v;   // exclusive within block
    if (tid == 1023) g_bsums[blockIdx.x] = s[1023];
}

// merged scan2+scan3 (256-thread blocks; arrays sized to blockDim) + sums zero
__global__ void k_scanfix() {
    __shared__ int s[256];
    __shared__ int sx[256];
    int tid = threadIdx.x;
    int v = (tid < NB_SCAN) ? g_bsums[tid] : 0;
    s[tid] = v;
    __syncthreads();
    for (int off = 1; off < 128; off <<= 1) {
        int t = (tid >= off) ? s[tid - off] : 0;
        __syncthreads();
        s[tid] += t;
        __syncthreads();
    }
    sx[tid] = s[tid] - v;   // exclusive
    __syncthreads();
    int i = blockIdx.x * blockDim.x + tid;
    if (i < CN) g_rowptr[i] += sx[i >> 10];
    if (blockIdx.x == 0)
        for (int j = tid; j < 6 * CH; j += blockDim.x) g_sums[j] = 0.f;
}

__global__ void k_scatter(const int* __restrict__ ei) {
    int e = blockIdx.x * blockDim.x + threadIdx.x;
    if (e < CE) {
        int d = ei[CE + e];
        int p = atomicAdd(&g_cursor[d], 1);
        g_col[g_rowptr[d] + p] = ei[e];
    }
}

// ---------------- aggregation: out = A_norm @ x ----------------
// Layer 0: raw x [N,32], one warp per node, one feature per lane.
__global__ void __launch_bounds__(256) k_agg32(const float* __restrict__ x) {
    int warp = (blockIdx.x * blockDim.x + threadIdx.x) >> 5;
    if (warp >= CN) return;
    int lane = threadIdx.x & 31;
    float dv = g_dinv[warp];
    float acc = dv * dv * x[(size_t)warp * CF + lane];   // self loop
    int e = g_rowptr[warp];
    int e1 = e + g_deg[warp];
    for (; e + 3 < e1; e += 4) {
        int s0 = g_col[e], s1 = g_col[e + 1], s2 = g_col[e + 2], s3 = g_col[e + 3];
        float w0 = g_dinv[s0] * dv, w1 = g_dinv[s1] * dv;
        float w2 = g_dinv[s2] * dv, w3 = g_dinv[s3] * dv;
        acc = fmaf(w0, x[(size_t)s0 * CF + lane], acc);
        acc = fmaf(w1, x[(size_t)s1 * CF + lane], acc);
        acc = fmaf(w2, x[(size_t)s2 * CF + lane], acc);
        acc = fmaf(w3, x[(size_t)s3 * CF + lane], acc);
    }
    for (; e < e1; e++) {
        int s = g_col[e];
        acc = fmaf(g_dinv[s] * dv, x[(size_t)s * CF + lane], acc);
    }
    g_bufA[(size_t)warp * CF + lane] = acc;
}

// Layers 1/2: fuse BN+ReLU into the gather; 4-edge unroll for MLP.
__global__ void __launch_bounds__(256) k_agg128(const float* __restrict__ xin,
                                                const float* __restrict__ scale,
                                                const float* __restrict__ shift,
                                                float* __restrict__ out) {
    int warp = (blockIdx.x * blockDim.x + threadIdx.x) >> 5;
    if (warp >= CN) return;
    int lane = threadIdx.x & 31;
    float4 sc = ((const float4*)scale)[lane];
    float4 sh = ((const float4*)shift)[lane];
    float dv = g_dinv[warp];
    float4 v = ((const float4*)(xin + (size_t)warp * CH))[lane];
    v = bnrelu4(v, sc, sh);
    float dv2 = dv * dv;
    float4 acc = make_float4(dv2 * v.x, dv2 * v.y, dv2 * v.z, dv2 * v.w);
    int e = g_rowptr[warp];
    int e1 = e + g_deg[warp];
    for (; e + 3 < e1; e += 4) {
        int s0 = g_col[e], s1 = g_col[e + 1], s2 = g_col[e + 2], s3 = g_col[e + 3];
        float w0 = g_dinv[s0] * dv, w1 = g_dinv[s1] * dv;
        float w2 = g_dinv[s2] * dv, w3 = g_dinv[s3] * dv;
        float4 u0 = ((const float4*)(xin + (size_t)s0 * CH))[lane];
        float4 u1 = ((const float4*)(xin + (size_t)s1 * CH))[lane];
        float4 u2 = ((const float4*)(xin + (size_t)s2 * CH))[lane];
        float4 u3 = ((const float4*)(xin + (size_t)s3 * CH))[lane];
        u0 = bnrelu4(u0, sc, sh);
        u1 = bnrelu4(u1, sc, sh);
        u2 = bnrelu4(u2, sc, sh);
        u3 = bnrelu4(u3, sc, sh);
        acc.x = fmaf(w0, u0.x, acc.x); acc.y = fmaf(w0, u0.y, acc.y);
        acc.z = fmaf(w0, u0.z, acc.z); acc.w = fmaf(w0, u0.w, acc.w);
        acc.x = fmaf(w1, u1.x, acc.x); acc.y = fmaf(w1, u1.y, acc.y);
        acc.z = fmaf(w1, u1.z, acc.z); acc.w = fmaf(w1, u1.w, acc.w);
        acc.x = fmaf(w2, u2.x, acc.x); acc.y = fmaf(w2, u2.y, acc.y);
        acc.z = fmaf(w2, u2.z, acc.z); acc.w = fmaf(w2, u2.w, acc.w);
        acc.x = fmaf(w3, u3.x, acc.x); acc.y = fmaf(w3, u3.y, acc.y);
        acc.z = fmaf(w3, u3.z, acc.z); acc.w = fmaf(w3, u3.w, acc.w);
    }
    for (; e < e1; e++) {
        int s = g_col[e];
        float w = g_dinv[s] * dv;
        float4 u = ((const float4*)(xin + (size_t)s * CH))[lane];
        u = bnrelu4(u, sc, sh);
        acc.x = fmaf(w, u.x, acc.x); acc.y = fmaf(w, u.y, acc.y);
        acc.z = fmaf(w, u.z, acc.z); acc.w = fmaf(w, u.w, acc.w);
    }
    ((float4*)(out + (size_t)warp * CH))[lane] = acc;
}

// ---------------- GEMM: out[N,128] = A[N,K] @ W[K,128] + bias, fused BN stats --
// Col-pair FFMA2: B pairs read directly as ulonglong2 (no packs), A dup via MOV.
template <int K>
__global__ void __launch_bounds__(256, 2) k_gemm(const float* __restrict__ A,
                                                 const float* __restrict__ W,
                                                 const float* __restrict__ bias,
                                                 float* __restrict__ out,
                                                 float* __restrict__ sums) {
    extern __shared__ float sm[];
    float* Ws = sm;               // [K][128]
    float* As = sm + K * 128;     // [32][ASTR] k-major chunk
    int tid = threadIdx.x;
    int tx = tid & 15;
    int ty = tid >> 4;
    int row0 = blockIdx.x * 128;

    for (int i = tid; i < K * 128; i += 256) Ws[i] = W[i];

    unsigned long long acc[8][4];   // 8 rows x 4 col-pairs
#pragma unroll
    for (int i = 0; i < 8; i++)
#pragma unroll
        for (int j = 0; j < 4; j++) acc[i][j] = 0ull;

    for (int kc = 0; kc < K; kc += 32) {
        __syncthreads();
        for (int i = tid; i < 128 * 32; i += 256) {
            int r = i >> 5, k = i & 31;
            int gr = row0 + r;
            As[k * ASTR + r] = (gr < CN) ? A[(size_t)gr * K + kc + k] : 0.f;
        }
        __syncthreads();
#pragma unroll
        for (int k = 0; k < 32; k++) {
            float4 a0 = *(const float4*)&As[k * ASTR + ty * 8];
            float4 a1 = *(const float4*)&As[k * ASTR + ty * 8 + 4];
            const ulonglong2* Brow = (const ulonglong2*)&Ws[(kc + k) * 128 + tx * 8];
            ulonglong2 q0 = Brow[0];
            ulonglong2 q1 = Brow[1];
            unsigned long long bp[4] = {q0.x, q0.y, q1.x, q1.y};
            float av[8] = {a0.x, a0.y, a0.z, a0.w, a1.x, a1.y, a1.z, a1.w};
#pragma unroll
            for (int i = 0; i < 8; i++) {
                unsigned long long ap = pack2(av[i], av[i]);
#pragma unroll
                for (int j = 0; j < 4; j++) ffma2(acc[i][j], ap, bp[j]);
            }
        }
    }

    // epilogue: + bias, store, per-column partial stats
    float4 bj0 = *(const float4*)&bias[tx * 8];
    float4 bj1 = *(const float4*)&bias[tx * 8 + 4];
    float bj[8] = {bj0.x, bj0.y, bj0.z, bj0.w, bj1.x, bj1.y, bj1.z, bj1.w};
    float csum[8], csq[8];
#pragma unroll
    for (int j = 0; j < 8; j++) { csum[j] = 0.f; csq[j] = 0.f; }
#pragma unroll
    for (int i = 0; i < 8; i++) {
        int r = row0 + ty * 8 + i;
        if (r < CN) {
            float v[8];
#pragma unroll
            for (int j = 0; j < 4; j++) unpack2(acc[i][j], v[2 * j], v[2 * j + 1]);
#pragma unroll
            for (int j = 0; j < 8; j++) {
                v[j] += bj[j];
                csum[j] += v[j];
                csq[j] += v[j] * v[j];
            }
            float* orow = out + (size_t)r * 128 + tx * 8;
            *(float4*)&orow[0] = make_float4(v[0], v[1], v[2], v[3]);
            *(float4*)&orow[4] = make_float4(v[4], v[5], v[6], v[7]);
        }
    }
    // block reduce stats via smem, one atomic per column per block
    __syncthreads();
    float* red = sm;  // 16*128 floats
#pragma unroll
    for (int j = 0; j < 8; j++) red[ty * 128 + tx * 8 + j] = csum[j];
    __syncthreads();
    if (tid < 128) {
        float t = 0.f;
#pragma unroll
        for (int q = 0; q < 16; q++) t += red[q * 128 + tid];
        atomicAdd(&sums[tid], t);
    }
    __syncthreads();
#pragma unroll
    for (int j = 0; j < 8; j++) red[ty * 128 + tx * 8 + j] = csq[j];
    __syncthreads();
    if (tid < 128) {
        float t = 0.f;
#pragma unroll
        for (int q = 0; q < 16; q++) t += red[q * 128 + tid];
        atomicAdd(&sums[128 + tid], t);
    }
}

// ---------------- BN params from stats ----------------
__global__ void k_bnp(const float* __restrict__ sums, const float* __restrict__ g,
                      const float* __restrict__ beta, float* __restrict__ scale,
                      float* __restrict__ shift) {
    int c = threadIdx.x;
    float mean = sums[c] * (1.f / CN);
    float var = sums[128 + c] * (1.f / CN) - mean * mean;
    float sc = g[c] * rsqrtf(var + 1e-5f);
    scale[c] = sc;
    shift[c] = fmaf(-mean, sc, beta[c]);
}

// ---------------- fused pooling + MLP head (batch is sorted) ----------------
__global__ void __launch_bounds__(128) k_poolhead(const int* __restrict__ batch,
                                                  const float* __restrict__ scale,
                                                  const float* __restrict__ shift,
                                                  const float* __restrict__ Wh1,
                                                  const float* __restrict__ bh1,
                                                  const float* __restrict__ Wh2,
                                                  const float* __restrict__ bh2,
                                                  float* __restrict__ out) {
    __shared__ float row[128];
    __shared__ float red[64];
    int g = blockIdx.x;
    int t = threadIdx.x;  // 128 threads

    int lo = 0, hi = CN;
    while (lo < hi) { int m = (lo + hi) >> 1; if (batch[m] < g) lo = m + 1; else hi = m; }
    int start = lo;
    hi = CN;
    while (lo < hi) { int m = (lo + hi) >> 1; if (batch[m] < g + 1) lo = m + 1; else hi = m; }
    int end = lo;

    float sc = scale[t], sh = shift[t];
    float acc = 0.f;
    for (int i = start; i < end; i++)
        acc += fmaxf(fmaf(sc, g_bufB[(size_t)i * CH + t], sh), 0.f);
    float inv = 1.f / fmaxf((float)(end - start), 1.f);
    row[t] = acc * inv;
    __syncthreads();

    if (t < 64) {
        float a = bh1[t];
#pragma unroll 8
        for (int f = 0; f < 128; f++) a = fmaf(row[f], Wh1[f * 64 + t], a);
        a = fmaxf(a, 0.f);
        red[t] = a * Wh2[t];
    }
    __syncthreads();
    if (t < 32) {
        float v = red[t] + red[t + 32];
#pragma unroll
        for (int off = 16; off > 0; off >>= 1)
            v += __shfl_down_sync(0xffffffffu, v, off);
        if (t == 0) out[g] = v + bh2[0];
    }
}

// ---------------- launch ----------------
extern "C" void kernel_launch(void* const* d_in, const int* in_sizes, int n_in,
                              void* d_out, int out_size) {
    const float* x  = (const float*)d_in[0];
    const int* ei   = (const int*)d_in[1];     // int32 (JAX x64 disabled)
    const int* batch= (const int*)d_in[2];     // int32
    const float* W0 = (const float*)d_in[3];
    const float* b0 = (const float*)d_in[4];
    const float* g0 = (const float*)d_in[5];
    const float* be0= (const float*)d_in[6];
    const float* W1 = (const float*)d_in[7];
    const float* b1 = (const float*)d_in[8];
    const float* g1 = (const float*)d_in[9];
    const float* be1= (const float*)d_in[10];
    const float* W2 = (const float*)d_in[11];
    const float* b2 = (const float*)d_in[12];
    const float* g2 = (const float*)d_in[13];
    const float* be2= (const float*)d_in[14];
    const float* Wh1= (const float*)d_in[15];
    const float* bh1= (const float*)d_in[16];
    const float* Wh2= (const float*)d_in[17];
    const float* bh2= (const float*)d_in[18];
    float* out = (float*)d_out;

    void* p;
    cudaGetSymbolAddress(&p, g_deg);    int*   degp  = (int*)p;
    cudaGetSymbolAddress(&p, g_bufA);   float* bufA  = (float*)p;
    cudaGetSymbolAddress(&p, g_bufB);   float* bufB  = (float*)p;
    cudaGetSymbolAddress(&p, g_sums);   float* sums  = (float*)p;
    cudaGetSymbolAddress(&p, g_scale);  float* scale = (float*)p;
    cudaGetSymbolAddress(&p, g_shift);  float* shift = (float*)p;

    const int SM128 = (128 * 128 + 32 * ASTR) * 4;  // 82432 B
    const int SM32  = (32 * 128 + 32 * ASTR) * 4;   // 33280 B
    cudaFuncSetAttribute(k_gemm<128>, cudaFuncAttributeMaxDynamicSharedMemorySize, SM128);
    cudaFuncSetAttribute(k_gemm<32>,  cudaFuncAttributeMaxDynamicSharedMemorySize, SM32);

    const int gemmBlocks = (CN + 127) / 128;   // 782
    const int aggBlocks = (CN + 7) / 8;        // 12500

    cudaMemsetAsync(degp, 0, CN * sizeof(int));
    k_deg<<<(CE + 255) / 256, 256>>>(ei);
    k_scan1<<<NB_SCAN, 1024>>>();
    k_scanfix<<<(CN + 255) / 256, 256>>>();
    k_scatter<<<(CE + 255) / 256, 256>>>(ei);

    // Layer 0
    k_agg32<<<aggBlocks, 256>>>(x);
    k_gemm<32><<<gemmBlocks, 256, SM32>>>(bufA, W0, b0, bufB, sums);
    k_bnp<<<1, 128>>>(sums, g0, be0, scale, shift);

    // Layer 1
    k_agg128<<<aggBlocks, 256>>>(bufB, scale, shift, bufA);
    k_gemm<128><<<gemmBlocks, 256, SM128>>>(bufA, W1, b1, bufB, sums + 256);
    k_bnp<<<1, 128>>>(sums + 256, g1, be1, scale + 128, shift + 128);

    // Layer 2
    k_agg128<<<aggBlocks, 256>>>(bufB, scale + 128, shift + 128, bufA);
    k_gemm<128><<<gemmBlocks, 256, SM128>>>(bufA, W2, b2, bufB, sums + 512);
    k_bnp<<<1, 128>>>(sums + 512, g2, be2, scale + 256, shift + 256);

    // Fused pool + head
    k_poolhead<<<CG, 128>>>(batch, scale + 256, shift + 256, Wh1, bh1, Wh2, bh2, out);
}

// round 12
// speedup vs baseline: 1.3031x; 1.0633x over previous
#include <cuda_runtime.h>
#include <cuda_fp16.h>
#include <math.h>

// Problem constants (fixed shapes per reference)
#define CN 100000      // nodes
#define CE 1600000     // edges
#define CG 4096        // graphs
#define CH 128         // hidden
#define CF 32          // input features
#define NB_SCAN 98     // ceil(CN/1024)
#define ASTR 132       // float stride of smem A-tile rows (k-major)

// ---------------- device scratch (static, no allocation) ----------------
__device__ __align__(16) int   g_deg[CN];
__device__ __align__(16) int   g_rowptr[CN];
__device__ __align__(16) int   g_cursor[CN];
__device__ __align__(16) int   g_col[CE];
__device__ __align__(16) float g_dinv[CN];
__device__ __align__(16) float g_bufA[(size_t)CN * CH];       // fp32 agg output (GEMM A)
__device__ __align__(16) __half g_bufB16[(size_t)CN * CH];    // fp16 pre-BN hidden
__device__ __align__(16) __half g_x16[(size_t)CN * CF];       // fp16 input features
__device__ __align__(16) float g_sums[6 * CH];   // (sum, sumsq) x 3 layers
__device__ __align__(16) float g_scale[3 * CH];
__device__ __align__(16) float g_shift[3 * CH];
__device__ __align__(16) int   g_bsums[128];

// ---------------- packed fp32x2 helpers ----------------
__device__ __forceinline__ unsigned long long pack2(float lo, float hi) {
    unsigned long long r;
    asm("mov.b64 %0, {%1, %2};" : "=l"(r) : "f"(lo), "f"(hi));
    return r;
}
__device__ __forceinline__ void unpack2(unsigned long long v, float& lo, float& hi) {
    asm("mov.b64 {%0, %1}, %2;" : "=f"(lo), "=f"(hi) : "l"(v));
}
__device__ __forceinline__ void ffma2(unsigned long long& d, unsigned long long a,
                                      unsigned long long b) {
    asm("fma.rn.f32x2 %0, %1, %2, %0;" : "+l"(d) : "l"(a), "l"(b));
}

__device__ __forceinline__ float4 bnrelu4(float4 v, float4 sc, float4 sh) {
    float4 r;
    r.x = fmaxf(fmaf(sc.x, v.x, sh.x), 0.f);
    r.y = fmaxf(fmaf(sc.y, v.y, sh.y), 0.f);
    r.z = fmaxf(fmaf(sc.z, v.z, sh.z), 0.f);
    r.w = fmaxf(fmaf(sc.w, v.w, sh.w), 0.f);
    return r;
}

// load 4 consecutive fp16 as float4 (8-byte aligned)
__device__ __forceinline__ float4 ld_half4(const __half* p) {
    uint2 r = *(const uint2*)p;
    float2 a = __half22float2(*(__half2*)&r.x);
    float2 b = __half22float2(*(__half2*)&r.y);
    return make_float4(a.x, a.y, b.x, b.y);
}

// ---------------- x -> fp16 ----------------
__global__ void k_xcast(const float* __restrict__ x) {
    int i = blockIdx.x * blockDim.x + threadIdx.x;   // pair index
    if (i < CN * CF / 2) {
        float2 v = ((const float2*)x)[i];
        ((__half2*)g_x16)[i] = __floats2half2_rn(v.x, v.y);
    }
}

// ---------------- CSR build (edge_index is int32) ----------------
__global__ void k_deg(const int* __restrict__ ei) {
    int e = blockIdx.x * blockDim.x + threadIdx.x;
    if (e < CE) atomicAdd(&g_deg[ei[CE + e]], 1);
}

__global__ void k_scan1() {     // block scan; also dinv + cursor zero
    __shared__ int s[1024];
    int tid = threadIdx.x;
    int i = blockIdx.x * 1024 + tid;
    int v = (i < CN) ? g_deg[i] : 0;
    if (i < CN) {
        g_dinv[i] = rsqrtf((float)(v + 1));   // +1 self loop
        g_cursor[i] = 0;
    }
    s[tid] = v;
    __syncthreads();
    for (int off = 1; off < 1024; off <<= 1) {
        int t = (tid >= off) ? s[tid - off] : 0;
        __syncthreads();
        s[tid] += t;
        __syncthreads();
    }
    if (i < CN) g_rowptr[i] = s[tid] - v;   // exclusive within block
    if (tid == 1023) g_bsums[blockIdx.x] = s[1023];
}

// merged scan2+scan3 (256-thread blocks) + sums zero
__global__ void k_scanfix() {
    __shared__ int s[256];
    __shared__ int sx[256];
    int tid = threadIdx.x;
    int v = (tid < NB_SCAN) ? g_bsums[tid] : 0;
    s[tid] = v;
    __syncthreads();
    for (int off = 1; off < 128; off <<= 1) {
        int t = (tid >= off) ? s[tid - off] : 0;
        __syncthreads();
        s[tid] += t;
        __syncthreads();
    }
    sx[tid] = s[tid] - v;   // exclusive
    __syncthreads();
    int i = blockIdx.x * blockDim.x + tid;
    if (i < CN) g_rowptr[i] += sx[i >> 10];
    if (blockIdx.x == 0)
        for (int j = tid; j < 6 * CH; j += blockDim.x) g_sums[j] = 0.f;
}

__global__ void k_scatter(const int* __restrict__ ei) {
    int e = blockIdx.x * blockDim.x + threadIdx.x;
    if (e < CE) {
        int d = ei[CE + e];
        int p = atomicAdd(&g_cursor[d], 1);
        g_col[g_rowptr[d] + p] = ei[e];
    }
}

// ---------------- aggregation: out = A_norm @ x (x in fp16) ----------------
__global__ void __launch_bounds__(256) k_agg32() {
    int warp = (blockIdx.x * blockDim.x + threadIdx.x) >> 5;
    if (warp >= CN) return;
    int lane = threadIdx.x & 31;
    float dv = g_dinv[warp];
    float acc = dv * dv * __half2float(g_x16[(size_t)warp * CF + lane]);  // self loop
    int e = g_rowptr[warp];
    int e1 = e + g_deg[warp];
    for (; e + 3 < e1; e += 4) {
        int s0 = g_col[e], s1 = g_col[e + 1], s2 = g_col[e + 2], s3 = g_col[e + 3];
        float w0 = g_dinv[s0] * dv, w1 = g_dinv[s1] * dv;
        float w2 = g_dinv[s2] * dv, w3 = g_dinv[s3] * dv;
        acc = fmaf(w0, __half2float(g_x16[(size_t)s0 * CF + lane]), acc);
        acc = fmaf(w1, __half2float(g_x16[(size_t)s1 * CF + lane]), acc);
        acc = fmaf(w2, __half2float(g_x16[(size_t)s2 * CF + lane]), acc);
        acc = fmaf(w3, __half2float(g_x16[(size_t)s3 * CF + lane]), acc);
    }
    for (; e < e1; e++) {
        int s = g_col[e];
        acc = fmaf(g_dinv[s] * dv, __half2float(g_x16[(size_t)s * CF + lane]), acc);
    }
    g_bufA[(size_t)warp * CF + lane] = acc;
}

// Layers 1/2: fp16 gather source; BN+ReLU fused; 4-edge unroll.
__global__ void __launch_bounds__(256) k_agg128(const __half* __restrict__ xin,
                                                const float* __restrict__ scale,
                                                const float* __restrict__ shift,
                                                float* __restrict__ out) {
    int warp = (blockIdx.x * blockDim.x + threadIdx.x) >> 5;
    if (warp >= CN) return;
    int lane = threadIdx.x & 31;
    float4 sc = ((const float4*)scale)[lane];
    float4 sh = ((const float4*)shift)[lane];
    float dv = g_dinv[warp];
    float4 v = ld_half4(xin + (size_t)warp * CH + lane * 4);
    v = bnrelu4(v, sc, sh);
    float dv2 = dv * dv;
    float4 acc = make_float4(dv2 * v.x, dv2 * v.y, dv2 * v.z, dv2 * v.w);
    int e = g_rowptr[warp];
    int e1 = e + g_deg[warp];
    for (; e + 3 < e1; e += 4) {
        int s0 = g_col[e], s1 = g_col[e + 1], s2 = g_col[e + 2], s3 = g_col[e + 3];
        float w0 = g_dinv[s0] * dv, w1 = g_dinv[s1] * dv;
        float w2 = g_dinv[s2] * dv, w3 = g_dinv[s3] * dv;
        float4 u0 = ld_half4(xin + (size_t)s0 * CH + lane * 4);
        float4 u1 = ld_half4(xin + (size_t)s1 * CH + lane * 4);
        float4 u2 = ld_half4(xin + (size_t)s2 * CH + lane * 4);
        float4 u3 = ld_half4(xin + (size_t)s3 * CH + lane * 4);
        u0 = bnrelu4(u0, sc, sh);
        u1 = bnrelu4(u1, sc, sh);
        u2 = bnrelu4(u2, sc, sh);
        u3 = bnrelu4(u3, sc, sh);
        acc.x = fmaf(w0, u0.x, acc.x); acc.y = fmaf(w0, u0.y, acc.y);
        acc.z = fmaf(w0, u0.z, acc.z); acc.w = fmaf(w0, u0.w, acc.w);
        acc.x = fmaf(w1, u1.x, acc.x); acc.y = fmaf(w1, u1.y, acc.y);
        acc.z = fmaf(w1, u1.z, acc.z); acc.w = fmaf(w1, u1.w, acc.w);
        acc.x = fmaf(w2, u2.x, acc.x); acc.y = fmaf(w2, u2.y, acc.y);
        acc.z = fmaf(w2, u2.z, acc.z); acc.w = fmaf(w2, u2.w, acc.w);
        acc.x = fmaf(w3, u3.x, acc.x); acc.y = fmaf(w3, u3.y, acc.y);
        acc.z = fmaf(w3, u3.z, acc.z); acc.w = fmaf(w3, u3.w, acc.w);
    }
    for (; e < e1; e++) {
        int s = g_col[e];
        float w = g_dinv[s] * dv;
        float4 u = ld_half4(xin + (size_t)s * CH + lane * 4);
        u = bnrelu4(u, sc, sh);
        acc.x = fmaf(w, u.x, acc.x); acc.y = fmaf(w, u.y, acc.y);
        acc.z = fmaf(w, u.z, acc.z); acc.w = fmaf(w, u.w, acc.w);
    }
    ((float4*)(out + (size_t)warp * CH))[lane] = acc;
}

// ---------------- GEMM: h = A @ W + bias (fp32 compute), fp16 store, fp32 stats -
template <int K>
__global__ void __launch_bounds__(256, 2) k_gemm(const float* __restrict__ A,
                                                 const float* __restrict__ W,
                                                 const float* __restrict__ bias,
                                                 __half* __restrict__ out,
                                                 float* __restrict__ sums) {
    extern __shared__ float sm[];
    float* Ws = sm;               // [K][128]
    float* As = sm + K * 128;     // [32][ASTR] k-major chunk
    int tid = threadIdx.x;
    int tx = tid & 15;
    int ty = tid >> 4;
    int row0 = blockIdx.x * 128;

    for (int i = tid; i < K * 128; i += 256) Ws[i] = W[i];

    unsigned long long acc[8][4];   // 8 rows x 4 col-pairs
#pragma unroll
    for (int i = 0; i < 8; i++)
#pragma unroll
        for (int j = 0; j < 4; j++) acc[i][j] = 0ull;

    for (int kc = 0; kc < K; kc += 32) {
        __syncthreads();
        for (int i = tid; i < 128 * 32; i += 256) {
            int r = i >> 5, k = i & 31;
            int gr = row0 + r;
            As[k * ASTR + r] = (gr < CN) ? A[(size_t)gr * K + kc + k] : 0.f;
        }
        __syncthreads();
#pragma unroll
        for (int k = 0; k < 32; k++) {
            float4 a0 = *(const float4*)&As[k * ASTR + ty * 8];
            float4 a1 = *(const float4*)&As[k * ASTR + ty * 8 + 4];
            const ulonglong2* Brow = (const ulonglong2*)&Ws[(kc + k) * 128 + tx * 8];
            ulonglong2 q0 = Brow[0];
            ulonglong2 q1 = Brow[1];
            unsigned long long bp[4] = {q0.x, q0.y, q1.x, q1.y};
            float av[8] = {a0.x, a0.y, a0.z, a0.w, a1.x, a1.y, a1.z, a1.w};
#pragma unroll
            for (int i = 0; i < 8; i++) {
                unsigned long long ap = pack2(av[i], av[i]);
#pragma unroll
                for (int j = 0; j < 4; j++) ffma2(acc[i][j], ap, bp[j]);
            }
        }
    }

    // epilogue: + bias, fp32 stats, fp16 store
    float4 bj0 = *(const float4*)&bias[tx * 8];
    float4 bj1 = *(const float4*)&bias[tx * 8 + 4];
    float bj[8] = {bj0.x, bj0.y, bj0.z, bj0.w, bj1.x, bj1.y, bj1.z, bj1.w};
    float csum[8], csq[8];
#pragma unroll
    for (int j = 0; j < 8; j++) { csum[j] = 0.f; csq[j] = 0.f; }
#pragma unroll
    for (int i = 0; i < 8; i++) {
        int r = row0 + ty * 8 + i;
        if (r < CN) {
            float v[8];
#pragma unroll
            for (int j = 0; j < 4; j++) unpack2(acc[i][j], v[2 * j], v[2 * j + 1]);
#pragma unroll
            for (int j = 0; j < 8; j++) {
                v[j] += bj[j];
                csum[j] += v[j];
                csq[j] += v[j] * v[j];
            }
            __half2 h01 = __floats2half2_rn(v[0], v[1]);
            __half2 h23 = __floats2half2_rn(v[2], v[3]);
            __half2 h45 = __floats2half2_rn(v[4], v[5]);
            __half2 h67 = __floats2half2_rn(v[6], v[7]);
            uint4 pk;
            pk.x = *(unsigned*)&h01;
            pk.y = *(unsigned*)&h23;
            pk.z = *(unsigned*)&h45;
            pk.w = *(unsigned*)&h67;
            *(uint4*)(out + (size_t)r * 128 + tx * 8) = pk;
        }
    }
    // block reduce stats via smem, one atomic per column per block
    __syncthreads();
    float* red = sm;  // 16*128 floats
#pragma unroll
    for (int j = 0; j < 8; j++) red[ty * 128 + tx * 8 + j] = csum[j];
    __syncthreads();
    if (tid < 128) {
        float t = 0.f;
#pragma unroll
        for (int q = 0; q < 16; q++) t += red[q * 128 + tid];
        atomicAdd(&sums[tid], t);
    }
    __syncthreads();
#pragma unroll
    for (int j = 0; j < 8; j++) red[ty * 128 + tx * 8 + j] = csq[j];
    __syncthreads();
    if (tid < 128) {
        float t = 0.f;
#pragma unroll
        for (int q = 0; q < 16; q++) t += red[q * 128 + tid];
        atomicAdd(&sums[128 + tid], t);
    }
}

// ---------------- BN params from stats ----------------
__global__ void k_bnp(const float* __restrict__ sums, const float* __restrict__ g,
                      const float* __restrict__ beta, float* __restrict__ scale,
                      float* __restrict__ shift) {
    int c = threadIdx.x;
    float mean = sums[c] * (1.f / CN);
    float var = sums[128 + c] * (1.f / CN) - mean * mean;
    float sc = g[c] * rsqrtf(var + 1e-5f);
    scale[c] = sc;
    shift[c] = fmaf(-mean, sc, beta[c]);
}

// ---------------- fused pooling + MLP head (batch is sorted) ----------------
__global__ void __launch_bounds__(128) k_poolhead(const int* __restrict__ batch,
                                                  const float* __restrict__ scale,
                                                  const float* __restrict__ shift,
                                                  const float* __restrict__ Wh1,
                                                  const float* __restrict__ bh1,
                                                  const float* __restrict__ Wh2,
                                                  const float* __restrict__ bh2,
                                                  float* __restrict__ out) {
    __shared__ float row[128];
    __shared__ float red[64];
    int g = blockIdx.x;
    int t = threadIdx.x;  // 128 threads

    int lo = 0, hi = CN;
    while (lo < hi) { int m = (lo + hi) >> 1; if (batch[m] < g) lo = m + 1; else hi = m; }
    int start = lo;
    hi = CN;
    while (lo < hi) { int m = (lo + hi) >> 1; if (batch[m] < g + 1) lo = m + 1; else hi = m; }
    int end = lo;

    float sc = scale[t], sh = shift[t];
    float acc = 0.f;
    for (int i = start; i < end; i++)
        acc += fmaxf(fmaf(sc, __half2float(g_bufB16[(size_t)i * CH + t]), sh), 0.f);
    float inv = 1.f / fmaxf((float)(end - start), 1.f);
    row[t] = acc * inv;
    __syncthreads();

    if (t < 64) {
        float a = bh1[t];
#pragma unroll 8
        for (int f = 0; f < 128; f++) a = fmaf(row[f], Wh1[f * 64 + t], a);
        a = fmaxf(a, 0.f);
        red[t] = a * Wh2[t];
    }
    __syncthreads();
    if (t < 32) {
        float v = red[t] + red[t + 32];
#pragma unroll
        for (int off = 16; off > 0; off >>= 1)
            v += __shfl_down_sync(0xffffffffu, v, off);
        if (t == 0) out[g] = v + bh2[0];
    }
}

// ---------------- launch ----------------
extern "C" void kernel_launch(void* const* d_in, const int* in_sizes, int n_in,
                              void* d_out, int out_size) {
    const float* x  = (const float*)d_in[0];
    const int* ei   = (const int*)d_in[1];     // int32 (JAX x64 disabled)
    const int* batch= (const int*)d_in[2];     // int32
    const float* W0 = (const float*)d_in[3];
    const float* b0 = (const float*)d_in[4];
    const float* g0 = (const float*)d_in[5];
    const float* be0= (const float*)d_in[6];
    const float* W1 = (const float*)d_in[7];
    const float* b1 = (const float*)d_in[8];
    const float* g1 = (const float*)d_in[9];
    const float* be1= (const float*)d_in[10];
    const float* W2 = (const float*)d_in[11];
    const float* b2 = (const float*)d_in[12];
    const float* g2 = (const float*)d_in[13];
    const float* be2= (const float*)d_in[14];
    const float* Wh1= (const float*)d_in[15];
    const float* bh1= (const float*)d_in[16];
    const float* Wh2= (const float*)d_in[17];
    const float* bh2= (const float*)d_in[18];
    float* out = (float*)d_out;

    void* p;
    cudaGetSymbolAddress(&p, g_deg);     int*    degp   = (int*)p;
    cudaGetSymbolAddress(&p, g_bufA);    float*  bufA   = (float*)p;
    cudaGetSymbolAddress(&p, g_bufB16);  __half* bufB16 = (__half*)p;
    cudaGetSymbolAddress(&p, g_sums);    float*  sums   = (float*)p;
    cudaGetSymbolAddress(&p, g_scale);   float*  scale  = (float*)p;
    cudaGetSymbolAddress(&p, g_shift);   float*  shift  = (float*)p;

    const int SM128 = (128 * 128 + 32 * ASTR) * 4;  // 82432 B
    const int SM32  = (32 * 128 + 32 * ASTR) * 4;   // 33280 B
    cudaFuncSetAttribute(k_gemm<128>, cudaFuncAttributeMaxDynamicSharedMemorySize, SM128);
    cudaFuncSetAttribute(k_gemm<32>,  cudaFuncAttributeMaxDynamicSharedMemorySize, SM32);

    const int gemmBlocks = (CN + 127) / 128;   // 782
    const int aggBlocks = (CN + 7) / 8;        // 12500

    cudaMemsetAsync(degp, 0, CN * sizeof(int));
    k_xcast<<<(CN * CF / 2 + 255) / 256, 256>>>(x);
    k_deg<<<(CE + 255) / 256, 256>>>(ei);
    k_scan1<<<NB_SCAN, 1024>>>();
    k_scanfix<<<(CN + 255) / 256, 256>>>();
    k_scatter<<<(CE + 255) / 256, 256>>>(ei);

    // Layer 0
    k_agg32<<<aggBlocks, 256>>>();
    k_gemm<32><<<gemmBlocks, 256, SM32>>>(bufA, W0, b0, bufB16, sums);
    k_bnp<<<1, 128>>>(sums, g0, be0, scale, shift);

    // Layer 1
    k_agg128<<<aggBlocks, 256>>>(bufB16, scale, shift, bufA);
    k_gemm<128><<<gemmBlocks, 256, SM128>>>(bufA, W1, b1, bufB16, sums + 256);
    k_bnp<<<1, 128>>>(sums + 256, g1, be1, scale + 128, shift + 128);

    // Layer 2
    k_agg128<<<aggBlocks, 256>>>(bufB16, scale + 128, shift + 128, bufA);
    k_gemm<128><<<gemmBlocks, 256, SM128>>>(bufA, W2, b2, bufB16, sums + 512);
    k_bnp<<<1, 128>>>(sums + 512, g2, be2, scale + 256, shift + 256);

    // Fused pool + head
    k_poolhead<<<CG, 128>>>(batch, scale + 256, shift + 256, Wh1, bh1, Wh2, bh2, out);
}

// round 13
// speedup vs baseline: 1.3368x; 1.0259x over previous
#include <cuda_runtime.h>
#include <cuda_fp16.h>
#include <math.h>

// Problem constants (fixed shapes per reference)
#define CN 100000      // nodes
#define CE 1600000     // edges
#define CG 4096        // graphs
#define CH 128         // hidden
#define CF 32          // input features
#define NB_SCAN 98     // ceil(CN/1024)
#define ASTR 132       // float stride of smem A-tile rows (k-major)

// ---------------- device scratch (static, no allocation) ----------------
__device__ __align__(16) int   g_deg[CN];
__device__ __align__(16) int   g_rowptr[CN];
__device__ __align__(16) int   g_cursor[CN];
__device__ __align__(16) int   g_col[CE];
__device__ __align__(16) float g_dinv[CN];
__device__ __align__(16) __half g_bufA16[(size_t)CN * CH];    // fp16 agg output (GEMM A)
__device__ __align__(16) __half g_bufB16[(size_t)CN * CH];    // fp16 pre-BN hidden
__device__ __align__(16) __half g_x16[(size_t)CN * CF];       // fp16 input features
__device__ __align__(16) float g_sums[6 * CH];   // (sum, sumsq) x 3 layers
__device__ __align__(16) float g_scale[3 * CH];
__device__ __align__(16) float g_shift[3 * CH];
__device__ __align__(16) int   g_bsums[128];

// ---------------- packed fp32x2 helpers ----------------
__device__ __forceinline__ unsigned long long pack2(float lo, float hi) {
    unsigned long long r;
    asm("mov.b64 %0, {%1, %2};" : "=l"(r) : "f"(lo), "f"(hi));
    return r;
}
__device__ __forceinline__ void unpack2(unsigned long long v, float& lo, float& hi) {
    asm("mov.b64 {%0, %1}, %2;" : "=f"(lo), "=f"(hi) : "l"(v));
}
__device__ __forceinline__ void ffma2(unsigned long long& d, unsigned long long a,
                                      unsigned long long b) {
    asm("fma.rn.f32x2 %0, %1, %2, %0;" : "+l"(d) : "l"(a), "l"(b));
}

__device__ __forceinline__ float4 bnrelu4(float4 v, float4 sc, float4 sh) {
    float4 r;
    r.x = fmaxf(fmaf(sc.x, v.x, sh.x), 0.f);
    r.y = fmaxf(fmaf(sc.y, v.y, sh.y), 0.f);
    r.z = fmaxf(fmaf(sc.z, v.z, sh.z), 0.f);
    r.w = fmaxf(fmaf(sc.w, v.w, sh.w), 0.f);
    return r;
}

// load 4 consecutive fp16 as float4 (8-byte aligned)
__device__ __forceinline__ float4 ld_half4(const __half* p) {
    uint2 r = *(const uint2*)p;
    float2 a = __half22float2(*(__half2*)&r.x);
    float2 b = __half22float2(*(__half2*)&r.y);
    return make_float4(a.x, a.y, b.x, b.y);
}
// store float4 as 4 fp16 (8-byte aligned)
__device__ __forceinline__ void st_half4(__half* p, float4 v) {
    __half2 a = __floats2half2_rn(v.x, v.y);
    __half2 b = __floats2half2_rn(v.z, v.w);
    uint2 r;
    r.x = *(unsigned*)&a;
    r.y = *(unsigned*)&b;
    *(uint2*)p = r;
}

// ---------------- x -> fp16 ----------------
__global__ void k_xcast(const float* __restrict__ x) {
    int i = blockIdx.x * blockDim.x + threadIdx.x;   // pair index
    if (i < CN * CF / 2) {
        float2 v = ((const float2*)x)[i];
        ((__half2*)g_x16)[i] = __floats2half2_rn(v.x, v.y);
    }
}

// ---------------- CSR build (edge_index is int32) ----------------
__global__ void k_deg(const int* __restrict__ ei) {
    int e = blockIdx.x * blockDim.x + threadIdx.x;
    if (e < CE) atomicAdd(&g_deg[ei[CE + e]], 1);
}

__global__ void k_scan1() {     // block scan; also dinv + cursor zero
    __shared__ int s[1024];
    int tid = threadIdx.x;
    int i = blockIdx.x * 1024 + tid;
    int v = (i < CN) ? g_deg[i] : 0;
    if (i < CN) {
        g_dinv[i] = rsqrtf((float)(v + 1));   // +1 self loop
        g_cursor[i] = 0;
    }
    s[tid] = v;
    __syncthreads();
    for (int off = 1; off < 1024; off <<= 1) {
        int t = (tid >= off) ? s[tid - off] : 0;
        __syncthreads();
        s[tid] += t;
        __syncthreads();
    }
    if (i < CN) g_rowptr[i] = s[tid] - v;   // exclusive within block
    if (tid == 1023) g_bsums[blockIdx.x] = s[1023];
}

// merged scan2+scan3 (256-thread blocks) + sums zero
__global__ void k_scanfix() {
    __shared__ int s[256];
    __shared__ int sx[256];
    int tid = threadIdx.x;
    int v = (tid < NB_SCAN) ? g_bsums[tid] : 0;
    s[tid] = v;
    __syncthreads();
    for (int off = 1; off < 128; off <<= 1) {
        int t = (tid >= off) ? s[tid - off] : 0;
        __syncthreads();
        s[tid] += t;
        __syncthreads();
    }
    sx[tid] = s[tid] - v;   // exclusive
    __syncthreads();
    int i = blockIdx.x * blockDim.x + tid;
    if (i < CN) g_rowptr[i] += sx[i >> 10];
    if (blockIdx.x == 0)
        for (int j = tid; j < 6 * CH; j += blockDim.x) g_sums[j] = 0.f;
}

__global__ void k_scatter(const int* __restrict__ ei) {
    int e = blockIdx.x * blockDim.x + threadIdx.x;
    if (e < CE) {
        int d = ei[CE + e];
        int p = atomicAdd(&g_cursor[d], 1);
        g_col[g_rowptr[d] + p] = ei[e];
    }
}

// ---------------- aggregation: out = A_norm @ x (x in fp16) ----------------
__global__ void __launch_bounds__(256) k_agg32() {
    int warp = (blockIdx.x * blockDim.x + threadIdx.x) >> 5;
    if (warp >= CN) return;
    int lane = threadIdx.x & 31;
    float dv = g_dinv[warp];
    float acc = dv * dv * __half2float(g_x16[(size_t)warp * CF + lane]);  // self loop
    int e = g_rowptr[warp];
    int e1 = e + g_deg[warp];
    for (; e + 3 < e1; e += 4) {
        int s0 = g_col[e], s1 = g_col[e + 1], s2 = g_col[e + 2], s3 = g_col[e + 3];
        float w0 = g_dinv[s0] * dv, w1 = g_dinv[s1] * dv;
        float w2 = g_dinv[s2] * dv, w3 = g_dinv[s3] * dv;
        acc = fmaf(w0, __half2float(g_x16[(size_t)s0 * CF + lane]), acc);
        acc = fmaf(w1, __half2float(g_x16[(size_t)s1 * CF + lane]), acc);
        acc = fmaf(w2, __half2float(g_x16[(size_t)s2 * CF + lane]), acc);
        acc = fmaf(w3, __half2float(g_x16[(size_t)s3 * CF + lane]), acc);
    }
    for (; e < e1; e++) {
        int s = g_col[e];
        acc = fmaf(g_dinv[s] * dv, __half2float(g_x16[(size_t)s * CF + lane]), acc);
    }
    g_bufA16[(size_t)warp * CF + lane] = __float2half_rn(acc);
}

// Layers 1/2: fp16 gather source + fp16 output; BN+ReLU fused; 4-edge unroll.
__global__ void __launch_bounds__(256) k_agg128(const __half* __restrict__ xin,
                                                const float* __restrict__ scale,
                                                const float* __restrict__ shift,
                                                __half* __restrict__ out) {
    int warp = (blockIdx.x * blockDim.x + threadIdx.x) >> 5;
    if (warp >= CN) return;
    int lane = threadIdx.x & 31;
    float4 sc = ((const float4*)scale)[lane];
    float4 sh = ((const float4*)shift)[lane];
    float dv = g_dinv[warp];
    float4 v = ld_half4(xin + (size_t)warp * CH + lane * 4);
    v = bnrelu4(v, sc, sh);
    float dv2 = dv * dv;
    float4 acc = make_float4(dv2 * v.x, dv2 * v.y, dv2 * v.z, dv2 * v.w);
    int e = g_rowptr[warp];
    int e1 = e + g_deg[warp];
    for (; e + 3 < e1; e += 4) {
        int s0 = g_col[e], s1 = g_col[e + 1], s2 = g_col[e + 2], s3 = g_col[e + 3];
        float w0 = g_dinv[s0] * dv, w1 = g_dinv[s1] * dv;
        float w2 = g_dinv[s2] * dv, w3 = g_dinv[s3] * dv;
        float4 u0 = ld_half4(xin + (size_t)s0 * CH + lane * 4);
        float4 u1 = ld_half4(xin + (size_t)s1 * CH + lane * 4);
        float4 u2 = ld_half4(xin + (size_t)s2 * CH + lane * 4);
        float4 u3 = ld_half4(xin + (size_t)s3 * CH + lane * 4);
        u0 = bnrelu4(u0, sc, sh);
        u1 = bnrelu4(u1, sc, sh);
        u2 = bnrelu4(u2, sc, sh);
        u3 = bnrelu4(u3, sc, sh);
        acc.x = fmaf(w0, u0.x, acc.x); acc.y = fmaf(w0, u0.y, acc.y);
        acc.z = fmaf(w0, u0.z, acc.z); acc.w = fmaf(w0, u0.w, acc.w);
        acc.x = fmaf(w1, u1.x, acc.x); acc.y = fmaf(w1, u1.y, acc.y);
        acc.z = fmaf(w1, u1.z, acc.z); acc.w = fmaf(w1, u1.w, acc.w);
        acc.x = fmaf(w2, u2.x, acc.x); acc.y = fmaf(w2, u2.y, acc.y);
        acc.z = fmaf(w2, u2.z, acc.z); acc.w = fmaf(w2, u2.w, acc.w);
        acc.x = fmaf(w3, u3.x, acc.x); acc.y = fmaf(w3, u3.y, acc.y);
        acc.z = fmaf(w3, u3.z, acc.z); acc.w = fmaf(w3, u3.w, acc.w);
    }
    for (; e < e1; e++) {
        int s = g_col[e];
        float w = g_dinv[s] * dv;
        float4 u = ld_half4(xin + (size_t)s * CH + lane * 4);
        u = bnrelu4(u, sc, sh);
        acc.x = fmaf(w, u.x, acc.x); acc.y = fmaf(w, u.y, acc.y);
        acc.z = fmaf(w, u.z, acc.z); acc.w = fmaf(w, u.w, acc.w);
    }
    st_half4(out + (size_t)warp * CH + lane * 4, acc);
}

// ---------------- GEMM: h = A @ W + bias (fp32 compute), fp16 A/out, fp32 stats -
template <int K>
__global__ void __launch_bounds__(256, 2) k_gemm(const __half* __restrict__ A,
                                                 const float* __restrict__ W,
                                                 const float* __restrict__ bias,
                                                 __half* __restrict__ out,
                                                 float* __restrict__ sums) {
    extern __shared__ float sm[];
    float* Ws = sm;               // [K][128]
    float* As = sm + K * 128;     // [32][ASTR] k-major chunk
    int tid = threadIdx.x;
    int tx = tid & 15;
    int ty = tid >> 4;
    int row0 = blockIdx.x * 128;

    for (int i = tid; i < K * 128; i += 256) Ws[i] = W[i];

    unsigned long long acc[8][4];   // 8 rows x 4 col-pairs
#pragma unroll
    for (int i = 0; i < 8; i++)
#pragma unroll
        for (int j = 0; j < 4; j++) acc[i][j] = 0ull;

    for (int kc = 0; kc < K; kc += 32) {
        __syncthreads();
        for (int i = tid; i < 128 * 32; i += 256) {
            int r = i >> 5, k = i & 31;
            int gr = row0 + r;
            float v = (gr < CN) ? __half2float(A[(size_t)gr * K + kc + k]) : 0.f;
            As[k * ASTR + r] = v;
        }
        __syncthreads();
#pragma unroll
        for (int k = 0; k < 32; k++) {
            float4 a0 = *(const float4*)&As[k * ASTR + ty * 8];
            float4 a1 = *(const float4*)&As[k * ASTR + ty * 8 + 4];
            const ulonglong2* Brow = (const ulonglong2*)&Ws[(kc + k) * 128 + tx * 8];
            ulonglong2 q0 = Brow[0];
            ulonglong2 q1 = Brow[1];
            unsigned long long bp[4] = {q0.x, q0.y, q1.x, q1.y};
            float av[8] = {a0.x, a0.y, a0.z, a0.w, a1.x, a1.y, a1.z, a1.w};
#pragma unroll
            for (int i = 0; i < 8; i++) {
                unsigned long long ap = pack2(av[i], av[i]);
#pragma unroll
                for (int j = 0; j < 4; j++) ffma2(acc[i][j], ap, bp[j]);
            }
        }
    }

    // epilogue: + bias, fp32 stats, fp16 store
    float4 bj0 = *(const float4*)&bias[tx * 8];
    float4 bj1 = *(const float4*)&bias[tx * 8 + 4];
    float bj[8] = {bj0.x, bj0.y, bj0.z, bj0.w, bj1.x, bj1.y, bj1.z, bj1.w};
    float csum[8], csq[8];
#pragma unroll
    for (int j = 0; j < 8; j++) { csum[j] = 0.f; csq[j] = 0.f; }
#pragma unroll
    for (int i = 0; i < 8; i++) {
        int r = row0 + ty * 8 + i;
        if (r < CN) {
            float v[8];
#pragma unroll
            for (int j = 0; j < 4; j++) unpack2(acc[i][j], v[2 * j], v[2 * j + 1]);
#pragma unroll
            for (int j = 0; j < 8; j++) {
                v[j] += bj[j];
                csum[j] += v[j];
                csq[j] += v[j] * v[j];
            }
            __half2 h01 = __floats2half2_rn(v[0], v[1]);
            __half2 h23 = __floats2half2_rn(v[2], v[3]);
            __half2 h45 = __floats2half2_rn(v[4], v[5]);
            __half2 h67 = __floats2half2_rn(v[6], v[7]);
            uint4 pk;
            pk.x = *(unsigned*)&h01;
            pk.y = *(unsigned*)&h23;
            pk.z = *(unsigned*)&h45;
            pk.w = *(unsigned*)&h67;
            *(uint4*)(out + (size_t)r * 128 + tx * 8) = pk;
        }
    }
    // block reduce stats via smem, one atomic per column per block
    __syncthreads();
    float* red = sm;  // 16*128 floats
#pragma unroll
    for (int j = 0; j < 8; j++) red[ty * 128 + tx * 8 + j] = csum[j];
    __syncthreads();
    if (tid < 128) {
        float t = 0.f;
#pragma unroll
        for (int q = 0; q < 16; q++) t += red[q * 128 + tid];
        atomicAdd(&sums[tid], t);
    }
    __syncthreads();
#pragma unroll
    for (int j = 0; j < 8; j++) red[ty * 128 + tx * 8 + j] = csq[j];
    __syncthreads();
    if (tid < 128) {
        float t = 0.f;
#pragma unroll
        for (int q = 0; q < 16; q++) t += red[q * 128 + tid];
        atomicAdd(&sums[128 + tid], t);
    }
}

// ---------------- BN params from stats ----------------
__global__ void k_bnp(const float* __restrict__ sums, const float* __restrict__ g,
                      const float* __restrict__ beta, float* __restrict__ scale,
                      float* __restrict__ shift) {
    int c = threadIdx.x;
    float mean = sums[c] * (1.f / CN);
    float var = sums[128 + c] * (1.f / CN) - mean * mean;
    float sc = g[c] * rsqrtf(var + 1e-5f);
    scale[c] = sc;
    shift[c] = fmaf(-mean, sc, beta[c]);
}

// ---------------- fused pooling + MLP head (batch is sorted) ----------------
__global__ void __launch_bounds__(128) k_poolhead(const int* __restrict__ batch,
                                                  const float* __restrict__ scale,
                                                  const float* __restrict__ shift,
                                                  const float* __restrict__ Wh1,
                                                  const float* __restrict__ bh1,
                                                  const float* __restrict__ Wh2,
                                                  const float* __restrict__ bh2,
                                                  float* __restrict__ out) {
    __shared__ float row[128];
    __shared__ float red[64];
    int g = blockIdx.x;
    int t = threadIdx.x;  // 128 threads

    int lo = 0, hi = CN;
    while (lo < hi) { int m = (lo + hi) >> 1; if (batch[m] < g) lo = m + 1; else hi = m; }
    int start = lo;
    hi = CN;
    while (lo < hi) { int m = (lo + hi) >> 1; if (batch[m] < g + 1) lo = m + 1; else hi = m; }
    int end = lo;

    float sc = scale[t], sh = shift[t];
    float acc = 0.f;
    for (int i = start; i < end; i++)
        acc += fmaxf(fmaf(sc, __half2float(g_bufB16[(size_t)i * CH + t]), sh), 0.f);
    float inv = 1.f / fmaxf((float)(end - start), 1.f);
    row[t] = acc * inv;
    __syncthreads();

    if (t < 64) {
        float a = bh1[t];
#pragma unroll 8
        for (int f = 0; f < 128; f++) a = fmaf(row[f], Wh1[f * 64 + t], a);
        a = fmaxf(a, 0.f);
        red[t] = a * Wh2[t];
    }
    __syncthreads();
    if (t < 32) {
        float v = red[t] + red[t + 32];
#pragma unroll
        for (int off = 16; off > 0; off >>= 1)
            v += __shfl_down_sync(0xffffffffu, v, off);
        if (t == 0) out[g] = v + bh2[0];
    }
}

// ---------------- launch ----------------
extern "C" void kernel_launch(void* const* d_in, const int* in_sizes, int n_in,
                              void* d_out, int out_size) {
    const float* x  = (const float*)d_in[0];
    const int* ei   = (const int*)d_in[1];     // int32 (JAX x64 disabled)
    const int* batch= (const int*)d_in[2];     // int32
    const float* W0 = (const float*)d_in[3];
    const float* b0 = (const float*)d_in[4];
    const float* g0 = (const float*)d_in[5];
    const float* be0= (const float*)d_in[6];
    const float* W1 = (const float*)d_in[7];
    const float* b1 = (const float*)d_in[8];
    const float* g1 = (const float*)d_in[9];
    const float* be1= (const float*)d_in[10];
    const float* W2 = (const float*)d_in[11];
    const float* b2 = (const float*)d_in[12];
    const float* g2 = (const float*)d_in[13];
    const float* be2= (const float*)d_in[14];
    const float* Wh1= (const float*)d_in[15];
    const float* bh1= (const float*)d_in[16];
    const float* Wh2= (const float*)d_in[17];
    const float* bh2= (const float*)d_in[18];
    float* out = (float*)d_out;

    void* p;
    cudaGetSymbolAddress(&p, g_deg);     int*    degp   = (int*)p;
    cudaGetSymbolAddress(&p, g_bufA16);  __half* bufA16 = (__half*)p;
    cudaGetSymbolAddress(&p, g_bufB16);  __half* bufB16 = (__half*)p;
    cudaGetSymbolAddress(&p, g_sums);    float*  sums   = (float*)p;
    cudaGetSymbolAddress(&p, g_scale);   float*  scale  = (float*)p;
    cudaGetSymbolAddress(&p, g_shift);   float*  shift  = (float*)p;

    const int SM128 = (128 * 128 + 32 * ASTR) * 4;  // 82432 B
    const int SM32  = (32 * 128 + 32 * ASTR) * 4;   // 33280 B
    cudaFuncSetAttribute(k_gemm<128>, cudaFuncAttributeMaxDynamicSharedMemorySize, SM128);
    cudaFuncSetAttribute(k_gemm<32>,  cudaFuncAttributeMaxDynamicSharedMemorySize, SM32);

    const int gemmBlocks = (CN + 127) / 128;   // 782
    const int aggBlocks = (CN + 7) / 8;        // 12500

    cudaMemsetAsync(degp, 0, CN * sizeof(int));
    k_xcast<<<(CN * CF / 2 + 255) / 256, 256>>>(x);
    k_deg<<<(CE + 255) / 256, 256>>>(ei);
    k_scan1<<<NB_SCAN, 1024>>>();
    k_scanfix<<<(CN + 255) / 256, 256>>>();
    k_scatter<<<(CE + 255) / 256, 256>>>(ei);

    // Layer 0
    k_agg32<<<aggBlocks, 256>>>();
    k_gemm<32><<<gemmBlocks, 256, SM32>>>(bufA16, W0, b0, bufB16, sums);
    k_bnp<<<1, 128>>>(sums, g0, be0, scale, shift);

    // Layer 1
    k_agg128<<<aggBlocks, 256>>>(bufB16, scale, shift, bufA16);
    k_gemm<128><<<gemmBlocks, 256, SM128>>>(bufA16, W1, b1, bufB16, sums + 256);
    k_bnp<<<1, 128>>>(sums + 256, g1, be1, scale + 128, shift + 128);

    // Layer 2
    k_agg128<<<aggBlocks, 256>>>(bufB16, scale + 128, shift + 128, bufA16);
    k_gemm<128><<<gemmBlocks, 256, SM128>>>(bufA16, W2, b2, bufB16, sums + 512);
    k_bnp<<<1, 128>>>(sums + 512, g2, be2, scale + 256, shift + 256);

    // Fused pool + head
    k_poolhead<<<CG, 128>>>(batch, scale + 256, shift + 256, Wh1, bh1, Wh2, bh2, out);
}